// round 12
// baseline (speedup 1.0000x reference)
#include <cuda_runtime.h>
#include <cuda_bf16.h>
#include <cstdint>

#define NCAP 10240            // node capacity for P tables
#define GCAP 20032            // group capacity

// Scratch (device globals: no allocations allowed)
__device__ float g_P[3 * NCAP * 128];   // Pa | Pb | Pc, each [nodes][128]
__device__ float g_Gc[GCAP * 128];      // per-group ctx term (+ b1 folded)

// Prebuilt weight fragments: tables 0..2 = W1 parts (2048 u4), 3 = W2 (1024 u4)
__device__ uint4 g_Wf_hi[4][2048];
__device__ uint4 g_Wf_lo[4][2048];

// ---------------------------------------------------------------------------
// helpers
// ---------------------------------------------------------------------------
__device__ __forceinline__ uint32_t smem_u32(const void* p) {
  uint32_t a;
  asm("{ .reg .u64 t; cvta.to.shared.u64 t, %1; cvt.u32.u64 %0, t; }"
      : "=r"(a) : "l"(p));
  return a;
}

__device__ __forceinline__ uint32_t bpack(__nv_bfloat16 a, __nv_bfloat16 b) {
  __nv_bfloat162 t(a, b);          // .x = a (low half)
  return *reinterpret_cast<uint32_t*>(&t);
}

#define LDSM4(r0, r1, r2, r3, addr)                                          \
  asm volatile(                                                              \
      "ldmatrix.sync.aligned.m8n8.x4.shared.b16 {%0,%1,%2,%3}, [%4];"        \
      : "=r"(r0), "=r"(r1), "=r"(r2), "=r"(r3) : "r"(addr))

#define MMA16816(d, a0, a1, a2, a3, b0, b1)                                  \
  asm volatile(                                                              \
      "mma.sync.aligned.m16n8k16.row.col.f32.bf16.bf16.f32 "                 \
      "{%0,%1,%2,%3}, {%4,%5,%6,%7}, {%8,%9}, {%0,%1,%2,%3};"                \
      : "+f"((d)[0]), "+f"((d)[1]), "+f"((d)[2]), "+f"((d)[3])               \
      : "r"(a0), "r"(a1), "r"(a2), "r"(a3), "r"(b0), "r"(b1))

// truncate fp32 to bf16 (toward zero); exact residual in fp32
__device__ __forceinline__ float trunc_bf16(float v) {
  return __uint_as_float(__float_as_uint(v) & 0xffff0000u);
}

// Common A-tile geometry (shared by both MMA kernels)
#define AROW 272                       // bytes per 128-ch row (16-aligned halves)
#define HALF_OFF 144                   // byte offset of channels 64..127

// build one hi/lo B-fragment uint4 pair from two weight rows
__device__ __forceinline__ void build_bfrag(const float* w_base, int row_stride,
                                            int ng0, int ng1, int k0,
                                            uint4* hi, uint4* lo) {
  uint32_t hx[2], hy[2], lx[2], ly[2];
  const int ngs[2] = {ng0, ng1};
#pragma unroll
  for (int t = 0; t < 2; t++) {
    const float* wr = w_base + (size_t)ngs[t] * row_stride + k0;
    const float w00 = wr[0], w01 = wr[1], w10 = wr[8], w11 = wr[9];
    __nv_bfloat16 h00 = __float2bfloat16(w00);
    __nv_bfloat16 h01 = __float2bfloat16(w01);
    __nv_bfloat16 h10 = __float2bfloat16(w10);
    __nv_bfloat16 h11 = __float2bfloat16(w11);
    __nv_bfloat16 l00 = __float2bfloat16(w00 - __bfloat162float(h00));
    __nv_bfloat16 l01 = __float2bfloat16(w01 - __bfloat162float(h01));
    __nv_bfloat16 l10 = __float2bfloat16(w10 - __bfloat162float(h10));
    __nv_bfloat16 l11 = __float2bfloat16(w11 - __bfloat162float(h11));
    hx[t] = bpack(h00, h01); hy[t] = bpack(h10, h11);
    lx[t] = bpack(l00, l01); ly[t] = bpack(l10, l11);
  }
  *hi = make_uint4(hx[0], hy[0], hx[1], hy[1]);
  *lo = make_uint4(lx[0], ly[0], lx[1], ly[1]);
}

// ---------------------------------------------------------------------------
// Kernel 0: build all weight fragments ONCE into device globals.
// grid (8, 4): blockIdx.y = table (0..2 W1 part, 3 = W2), 256 thr.
// ---------------------------------------------------------------------------
__global__ __launch_bounds__(256) void build_wfrags(
    const float* __restrict__ W1, const float* __restrict__ W2) {
  const int tab = blockIdx.y;
  const int i = blockIdx.x * 256 + threadIdx.x;
  const int count = (tab == 3) ? 1024 : 2048;
  if (i >= count) return;

  const int ln = i & 31;
  const int npw = (tab == 3) ? ((i >> 5) & 3) : ((i >> 5) & 7);
  const int ks = (tab == 3) ? (i >> 7) : (i >> 8);
  const int k0 = ks * 16 + (ln & 3) * 2;
  const int ng0 = (2 * npw) * 8 + (ln >> 2);
  const int ng1 = (2 * npw + 1) * 8 + (ln >> 2);

  uint4 hi, lo;
  if (tab == 3) build_bfrag(W2, 128, ng0, ng1, k0, &hi, &lo);
  else          build_bfrag(W1 + tab * 128, 384, ng0, ng1, k0, &hi, &lo);
  g_Wf_hi[tab][i] = hi;
  g_Wf_lo[tab][i] = lo;
}

// ---------------------------------------------------------------------------
// Kernel A (tensor): P[p][n][j] = sum_k x[n][k] * W1[j][p*128+k]
// grid (ceil(ntiles/4), 3): blockIdx.y = part. Fragments COPIED coalesced
// from g_Wf (no scattered build). 4 warps x one 16-row x tile.
// ---------------------------------------------------------------------------
#define PP_AHI 0
#define PP_ALO (4 * 16 * AROW)             // 17408
#define PP_BHI (2 * 4 * 16 * AROW)         // 34816
#define PP_BLO (PP_BHI + 32768)            // 67584
#define PP_SMEM (PP_BLO + 32768)           // 100352

__global__ void __launch_bounds__(128, 2) precompute_P_tc(
    const float* __restrict__ x, int nodes) {
  extern __shared__ char smem[];
  const uint32_t sbase = smem_u32(smem);
  const int tid = threadIdx.x;
  const int wid = tid >> 5;
  const int lane = tid & 31;
  const int p = blockIdx.y;

  uint4* Bhi4 = (uint4*)(smem + PP_BHI);   // [ks][np][lane], np=0..7 (16 nf)
  uint4* Blo4 = (uint4*)(smem + PP_BLO);

  const int ntiles = (nodes + 15) >> 4;
  const int wt = blockIdx.x * 4 + wid;
  const bool active = (wt < ntiles);
  const int n0 = wt << 4;

  // ---- coalesced fragment copy from global (prebuilt) ----
  {
    const uint4* sh = g_Wf_hi[p];
    const uint4* sl = g_Wf_lo[p];
    for (int i = tid; i < 2048; i += 128) {
      Bhi4[i] = sh[i];
      Blo4[i] = sl[i];
    }
  }

  // ---- A split: 16 x-rows -> trunc hi/lo bf16 in AROW layout ----
  const int sub = lane & 7;
  const int rgl = lane >> 3;
  char* tile_hi = smem + PP_AHI + (size_t)wid * 16 * AROW;
  char* tile_lo = smem + PP_ALO + (size_t)wid * 16 * AROW;
  if (active) {
#pragma unroll
    for (int rg = 0; rg < 4; rg++) {
      const int r = rg * 4 + rgl;
      const int gr = min(n0 + r, nodes - 1);
      const float* xr = x + (size_t)gr * 128;
      char* rhi = tile_hi + (size_t)r * AROW;
      char* rlo = tile_lo + (size_t)r * AROW;
#pragma unroll
      for (int q = 0; q < 4; q++) {
        const int c = q * 32 + sub * 4;
        const float4 v4 = *(const float4*)(xr + c);
        const uint32_t hi01 = __byte_perm(__float_as_uint(v4.x),
                                          __float_as_uint(v4.y), 0x7632);
        const uint32_t hi23 = __byte_perm(__float_as_uint(v4.z),
                                          __float_as_uint(v4.w), 0x7632);
        const float l0 = v4.x - trunc_bf16(v4.x);
        const float l1 = v4.y - trunc_bf16(v4.y);
        const float l2 = v4.z - trunc_bf16(v4.z);
        const float l3 = v4.w - trunc_bf16(v4.w);
        const __nv_bfloat162 lp01 = __floats2bfloat162_rn(l0, l1);
        const __nv_bfloat162 lp23 = __floats2bfloat162_rn(l2, l3);
        const int qb = (q < 2) ? (q * 64 + sub * 8)
                               : (HALF_OFF + (q - 2) * 64 + sub * 8);
        *(uint2*)(rhi + qb) = make_uint2(hi01, hi23);
        *(uint2*)(rlo + qb) =
            make_uint2(*(const uint32_t*)&lp01, *(const uint32_t*)&lp23);
      }
    }
  }
  __syncthreads();

  if (!active) return;

  // ldmatrix addressing
  const uint32_t lrow = (lane < 16) ? lane : (lane - 16);
  const uint32_t lcol = (lane < 16) ? 0u : 16u;
  const uint32_t ahi_ld = sbase + PP_AHI + (wid * 16 + lrow) * AROW + lcol;
  const uint32_t alo_ld = sbase + PP_ALO + (wid * 16 + lrow) * AROW + lcol;

  float acc[16][4];
#pragma unroll
  for (int n = 0; n < 16; n++)
#pragma unroll
    for (int q = 0; q < 4; q++) acc[n][q] = 0.f;

#pragma unroll
  for (int ks = 0; ks < 8; ks++) {
    const uint32_t kb = ks * 32 + ((ks >= 4) ? 16u : 0u);
    uint32_t ah0, ah1, ah2, ah3, al0, al1, al2, al3;
    LDSM4(ah0, ah1, ah2, ah3, ahi_ld + kb);
    LDSM4(al0, al1, al2, al3, alo_ld + kb);
#pragma unroll
    for (int np = 0; np < 8; np++) {
      const uint4 vh = Bhi4[(ks * 8 + np) * 32 + lane];
      const uint4 vl = Blo4[(ks * 8 + np) * 32 + lane];
      MMA16816(acc[2 * np], ah0, ah1, ah2, ah3, vh.x, vh.y);
      MMA16816(acc[2 * np], ah0, ah1, ah2, ah3, vl.x, vl.y);
      MMA16816(acc[2 * np], al0, al1, al2, al3, vh.x, vh.y);
      MMA16816(acc[2 * np + 1], ah0, ah1, ah2, ah3, vh.z, vh.w);
      MMA16816(acc[2 * np + 1], ah0, ah1, ah2, ah3, vl.z, vl.w);
      MMA16816(acc[2 * np + 1], al0, al1, al2, al3, vh.z, vh.w);
    }
  }

  // store D -> g_P[p]; fragment mapping: rows lane>>2 and +8, cols nf*8+(lane&3)*2
  float* Pp = g_P + (size_t)p * NCAP * 128;
  const int r0 = n0 + (lane >> 2);
  const int r1 = r0 + 8;
#pragma unroll
  for (int nf = 0; nf < 16; nf++) {
    const int c0 = nf * 8 + (lane & 3) * 2;
    if (r0 < nodes)
      *(float2*)(Pp + (size_t)r0 * 128 + c0) = make_float2(acc[nf][0], acc[nf][1]);
    if (r1 < nodes)
      *(float2*)(Pp + (size_t)r1 * 128 + c0) = make_float2(acc[nf][2], acc[nf][3]);
  }
}

// ---------------------------------------------------------------------------
// Kernel B: per-group context term (+ b1 folded in)
// ---------------------------------------------------------------------------
__global__ __launch_bounds__(128) void group_ctx(
    const int* __restrict__ indices, const float* __restrict__ b1, int G) {
  const int g = blockIdx.x;
  if (g >= G) return;
  const int t = threadIdx.x;
  const int* ip = indices + (size_t)g * 25 * 23 + 3;
  const float* Pc = g_P + (size_t)2 * NCAP * 128;

  float s = 0.f;
  int cnt = 0;
#pragma unroll
  for (int kk = 0; kk < 20; kk++) {
    const int id = ip[kk];
    s += Pc[(size_t)id * 128 + t];
    cnt += (id > 0) ? 1 : 0;
  }
  const float norm = (float)(cnt > 0 ? cnt : 1);
  g_Gc[(size_t)g * 128 + t] = s / norm + b1[t];
}

// ---------------------------------------------------------------------------
// Kernel C: warp-independent HMMA MLP. Each warp owns a 32-row tile
// (two 16-row subtiles) so every B-fragment LDS feeds 2 subtiles -> B smem
// wavefronts per row halved (B re-read was 46% of L1 traffic).
// 128-thread blocks (4 warps); smem unchanged; 2 blocks/SM.
// ---------------------------------------------------------------------------
#define AHI_OFF 0
#define ALO_OFF (4 * 32 * AROW)        // 34816
#define BF_OFF (2 * (4 * 32 * AROW))   // 69632
#define BFRAG_U4 1024                  // (8 ks * 4 np * 32 lanes) uint4 per pass
#define MISC_OFF (BF_OFF + 2 * BFRAG_U4 * 16)  // 102400
#define SMEM_BYTES (MISC_OFF + 768)

__global__ void __launch_bounds__(128) mlp_main_mma(
    const int* __restrict__ indices,
    const float* __restrict__ b2, const float* __restrict__ W3,
    const float* __restrict__ b3,
    float* __restrict__ out, int N) {
  extern __shared__ char smem[];
  const uint32_t sbase = smem_u32(smem);

  const int tid = threadIdx.x;
  const int wid = tid >> 5;
  const int lane = tid & 31;

  uint4* Bhi4 = (uint4*)(smem + BF_OFF);     // [ks][np][lane]
  uint4* Blo4 = Bhi4 + BFRAG_U4;
  float* b2s = (float*)(smem + MISC_OFF);
  float* w3s = b2s + 64;

  // ---- coalesced W2 fragment copy (prebuilt, table 3) ----
  {
    const uint4* sh = g_Wf_hi[3];
    const uint4* sl = g_Wf_lo[3];
    for (int i = tid; i < BFRAG_U4; i += 128) {
      Bhi4[i] = sh[i];
      Blo4[i] = sl[i];
    }
  }
  if (tid < 64) { b2s[tid] = b2[tid]; w3s[tid] = W3[tid]; }
  const float b3v = b3[0];
  __syncthreads();

  const float* Pa = g_P;
  const float* Pb = g_P + (size_t)NCAP * 128;

  const int sub = lane & 7;          // 16B sub-block within a 128B line
  const int rgl = lane >> 3;         // row within group of 4
  char* tile_hi = smem + AHI_OFF + (size_t)(wid * 32) * AROW;
  char* tile_lo = smem + ALO_OFF + (size_t)(wid * 32) * AROW;

  const uint32_t lrow = (lane < 16) ? lane : (lane - 16);
  const uint32_t lcol = (lane < 16) ? 0u : 16u;
  const uint32_t ahi_ld = sbase + AHI_OFF + (wid * 32 + lrow) * AROW + lcol;
  const uint32_t alo_ld = sbase + ALO_OFF + (wid * 32 + lrow) * AROW + lcol;

  const int NTW = (N + 31) >> 5;     // 32-row warp tiles
  const int wstride = gridDim.x * 4;

  for (int wt = blockIdx.x * 4 + wid; wt < NTW; wt += wstride) {
    const int rbase = wt << 5;

    // ---- Phase A: gather 32 rows + relu + truncation bf16 hi/lo split ----
#pragma unroll
    for (int rg = 0; rg < 8; rg++) {
      const int r = rg * 4 + rgl;
      const int gr = min(rbase + r, N - 1);
      const int i0 = indices[(size_t)gr * 23 + 0];
      const int i1 = indices[(size_t)gr * 23 + 1];
      const int g = gr / 25;
      const float* pa = Pa + (size_t)i0 * 128;
      const float* pb = Pb + (size_t)i1 * 128;
      const float* gc = g_Gc + (size_t)g * 128;
      char* rhi = tile_hi + (size_t)r * AROW;
      char* rlo = tile_lo + (size_t)r * AROW;
#pragma unroll
      for (int q = 0; q < 4; q++) {
        const int c = q * 32 + sub * 4;
        const float4 va = *(const float4*)(pa + c);
        const float4 vb = *(const float4*)(pb + c);
        const float4 vg = *(const float4*)(gc + c);
        float v0 = fmaxf(va.x + vb.x + vg.x, 0.f);
        float v1 = fmaxf(va.y + vb.y + vg.y, 0.f);
        float v2 = fmaxf(va.z + vb.z + vg.z, 0.f);
        float v3 = fmaxf(va.w + vb.w + vg.w, 0.f);
        const uint32_t hi01 =
            __byte_perm(__float_as_uint(v0), __float_as_uint(v1), 0x7632);
        const uint32_t hi23 =
            __byte_perm(__float_as_uint(v2), __float_as_uint(v3), 0x7632);
        const float l0 = v0 - trunc_bf16(v0);
        const float l1 = v1 - trunc_bf16(v1);
        const float l2 = v2 - trunc_bf16(v2);
        const float l3 = v3 - trunc_bf16(v3);
        const __nv_bfloat162 lp01 = __floats2bfloat162_rn(l0, l1);
        const __nv_bfloat162 lp23 = __floats2bfloat162_rn(l2, l3);
        const int qb = (q < 2) ? (q * 64 + sub * 8)
                               : (HALF_OFF + (q - 2) * 64 + sub * 8);
        *(uint2*)(rhi + qb) = make_uint2(hi01, hi23);
        *(uint2*)(rlo + qb) =
            make_uint2(*(const uint32_t*)&lp01, *(const uint32_t*)&lp23);
      }
    }
    __syncwarp();

    // ---- Phase B: 3-pass HMMA on two 16-row subtiles per B-frag load ----
    float acc[2][8][4];
#pragma unroll
    for (int t = 0; t < 2; t++)
#pragma unroll
      for (int n = 0; n < 8; n++)
#pragma unroll
        for (int q = 0; q < 4; q++) acc[t][n][q] = 0.f;

#pragma unroll
    for (int ks = 0; ks < 8; ks++) {
      const uint32_t kb = ks * 32 + ((ks >= 4) ? 16u : 0u);
      uint32_t a0h0, a0h1, a0h2, a0h3, a0l0, a0l1, a0l2, a0l3;
      uint32_t a1h0, a1h1, a1h2, a1h3, a1l0, a1l1, a1l2, a1l3;
      LDSM4(a0h0, a0h1, a0h2, a0h3, ahi_ld + kb);
      LDSM4(a0l0, a0l1, a0l2, a0l3, alo_ld + kb);
      LDSM4(a1h0, a1h1, a1h2, a1h3, ahi_ld + 16 * AROW + kb);
      LDSM4(a1l0, a1l1, a1l2, a1l3, alo_ld + 16 * AROW + kb);
#pragma unroll
      for (int np = 0; np < 4; np++) {
        const uint4 vh = Bhi4[(ks * 4 + np) * 32 + lane];
        const uint4 vl = Blo4[(ks * 4 + np) * 32 + lane];
        MMA16816(acc[0][2 * np], a0h0, a0h1, a0h2, a0h3, vh.x, vh.y);
        MMA16816(acc[0][2 * np], a0h0, a0h1, a0h2, a0h3, vl.x, vl.y);
        MMA16816(acc[0][2 * np], a0l0, a0l1, a0l2, a0l3, vh.x, vh.y);
        MMA16816(acc[0][2 * np + 1], a0h0, a0h1, a0h2, a0h3, vh.z, vh.w);
        MMA16816(acc[0][2 * np + 1], a0h0, a0h1, a0h2, a0h3, vl.z, vl.w);
        MMA16816(acc[0][2 * np + 1], a0l0, a0l1, a0l2, a0l3, vh.z, vh.w);
        MMA16816(acc[1][2 * np], a1h0, a1h1, a1h2, a1h3, vh.x, vh.y);
        MMA16816(acc[1][2 * np], a1h0, a1h1, a1h2, a1h3, vl.x, vl.y);
        MMA16816(acc[1][2 * np], a1l0, a1l1, a1l2, a1l3, vh.x, vh.y);
        MMA16816(acc[1][2 * np + 1], a1h0, a1h1, a1h2, a1h3, vh.z, vh.w);
        MMA16816(acc[1][2 * np + 1], a1h0, a1h1, a1h2, a1h3, vl.z, vl.w);
        MMA16816(acc[1][2 * np + 1], a1l0, a1l1, a1l2, a1l3, vh.z, vh.w);
      }
    }

    // ---- Epilogue (per subtile) ----
#pragma unroll
    for (int t = 0; t < 2; t++) {
      float s0 = 0.f, s1 = 0.f;
#pragma unroll
      for (int n = 0; n < 8; n++) {
        const int c0 = n * 8 + (lane & 3) * 2;
        const float2 b2p = *(const float2*)(b2s + c0);
        const float2 w3p = *(const float2*)(w3s + c0);
        s0 = fmaf(fmaxf(acc[t][n][0] + b2p.x, 0.f), w3p.x, s0);
        s0 = fmaf(fmaxf(acc[t][n][1] + b2p.y, 0.f), w3p.y, s0);
        s1 = fmaf(fmaxf(acc[t][n][2] + b2p.x, 0.f), w3p.x, s1);
        s1 = fmaf(fmaxf(acc[t][n][3] + b2p.y, 0.f), w3p.y, s1);
      }
      s0 += __shfl_xor_sync(0xffffffffu, s0, 1);
      s0 += __shfl_xor_sync(0xffffffffu, s0, 2);
      s1 += __shfl_xor_sync(0xffffffffu, s1, 1);
      s1 += __shfl_xor_sync(0xffffffffu, s1, 2);
      if ((lane & 3) == 0) {
        const int r0 = rbase + t * 16 + (lane >> 2);
        if (r0 < N) out[r0] = s0 + b3v;
        const int r1 = r0 + 8;
        if (r1 < N) out[r1] = s1 + b3v;
      }
    }
    __syncwarp();   // protect smem tile reuse next iteration
  }
}

// ---------------------------------------------------------------------------
extern "C" void kernel_launch(void* const* d_in, const int* in_sizes, int n_in,
                              void* d_out, int out_size) {
  const int* indices = (const int*)d_in[0];
  // d_in[1] = nr (fixed 24)
  const float* x  = (const float*)d_in[2];
  const float* W1 = (const float*)d_in[3];
  const float* b1 = (const float*)d_in[4];
  const float* W2 = (const float*)d_in[5];
  const float* b2 = (const float*)d_in[6];
  const float* W3 = (const float*)d_in[7];
  const float* b3 = (const float*)d_in[8];
  float* out = (float*)d_out;

  const int N = in_sizes[0] / 23;          // 500000
  const int nodes = in_sizes[2] / 128;     // 10000
  const int G = (N - 2) / 25 + 1;          // 20000 groups
  const int ntiles = (nodes + 15) / 16;    // 625

  cudaFuncSetAttribute(precompute_P_tc,
                       cudaFuncAttributeMaxDynamicSharedMemorySize, PP_SMEM);
  cudaFuncSetAttribute(mlp_main_mma,
                       cudaFuncAttributeMaxDynamicSharedMemorySize, SMEM_BYTES);

  dim3 gridW(8, 4);
  build_wfrags<<<gridW, 256>>>(W1, W2);
  dim3 gridP((ntiles + 3) / 4, 3);
  precompute_P_tc<<<gridP, 128, PP_SMEM>>>(x, nodes);
  group_ctx<<<G, 128>>>(indices, b1, G);
  mlp_main_mma<<<296, 128, SMEM_BYTES>>>(indices, b2, W3, b3, out, N);
}

// round 13
// speedup vs baseline: 1.0337x; 1.0337x over previous
#include <cuda_runtime.h>
#include <cuda_bf16.h>
#include <cstdint>

#define NCAP 10240            // node capacity for P tables
#define GCAP 20032            // group capacity

// Scratch (device globals: no allocations allowed)
__device__ float g_P[3 * NCAP * 128];   // Pa | Pb | Pc, each [nodes][128]
__device__ float g_Gc[GCAP * 128];      // per-group ctx term (+ b1 folded)

// Prebuilt weight fragments: tables 0..2 = W1 parts (2048 u4), 3 = W2 (1024 u4)
__device__ uint4 g_Wf_hi[4][2048];
__device__ uint4 g_Wf_lo[4][2048];

// ---------------------------------------------------------------------------
// helpers
// ---------------------------------------------------------------------------
__device__ __forceinline__ uint32_t smem_u32(const void* p) {
  uint32_t a;
  asm("{ .reg .u64 t; cvta.to.shared.u64 t, %1; cvt.u32.u64 %0, t; }"
      : "=r"(a) : "l"(p));
  return a;
}

__device__ __forceinline__ uint32_t bpack(__nv_bfloat16 a, __nv_bfloat16 b) {
  __nv_bfloat162 t(a, b);          // .x = a (low half)
  return *reinterpret_cast<uint32_t*>(&t);
}

#define LDSM4(r0, r1, r2, r3, addr)                                          \
  asm volatile(                                                              \
      "ldmatrix.sync.aligned.m8n8.x4.shared.b16 {%0,%1,%2,%3}, [%4];"        \
      : "=r"(r0), "=r"(r1), "=r"(r2), "=r"(r3) : "r"(addr))

#define MMA16816(d, a0, a1, a2, a3, b0, b1)                                  \
  asm volatile(                                                              \
      "mma.sync.aligned.m16n8k16.row.col.f32.bf16.bf16.f32 "                 \
      "{%0,%1,%2,%3}, {%4,%5,%6,%7}, {%8,%9}, {%0,%1,%2,%3};"                \
      : "+f"((d)[0]), "+f"((d)[1]), "+f"((d)[2]), "+f"((d)[3])               \
      : "r"(a0), "r"(a1), "r"(a2), "r"(a3), "r"(b0), "r"(b1))

// truncate fp32 to bf16 (toward zero); exact residual in fp32
__device__ __forceinline__ float trunc_bf16(float v) {
  return __uint_as_float(__float_as_uint(v) & 0xffff0000u);
}

// Common A-tile geometry (shared by both MMA kernels)
#define AROW 272                       // bytes per 128-ch row (16-aligned halves)
#define HALF_OFF 144                   // byte offset of channels 64..127

// build one hi/lo B-fragment uint4 pair from two weight rows
__device__ __forceinline__ void build_bfrag(const float* w_base, int row_stride,
                                            int ng0, int ng1, int k0,
                                            uint4* hi, uint4* lo) {
  uint32_t hx[2], hy[2], lx[2], ly[2];
  const int ngs[2] = {ng0, ng1};
#pragma unroll
  for (int t = 0; t < 2; t++) {
    const float* wr = w_base + (size_t)ngs[t] * row_stride + k0;
    const float w00 = wr[0], w01 = wr[1], w10 = wr[8], w11 = wr[9];
    __nv_bfloat16 h00 = __float2bfloat16(w00);
    __nv_bfloat16 h01 = __float2bfloat16(w01);
    __nv_bfloat16 h10 = __float2bfloat16(w10);
    __nv_bfloat16 h11 = __float2bfloat16(w11);
    __nv_bfloat16 l00 = __float2bfloat16(w00 - __bfloat162float(h00));
    __nv_bfloat16 l01 = __float2bfloat16(w01 - __bfloat162float(h01));
    __nv_bfloat16 l10 = __float2bfloat16(w10 - __bfloat162float(h10));
    __nv_bfloat16 l11 = __float2bfloat16(w11 - __bfloat162float(h11));
    hx[t] = bpack(h00, h01); hy[t] = bpack(h10, h11);
    lx[t] = bpack(l00, l01); ly[t] = bpack(l10, l11);
  }
  *hi = make_uint4(hx[0], hy[0], hx[1], hy[1]);
  *lo = make_uint4(lx[0], ly[0], lx[1], ly[1]);
}

// ---------------------------------------------------------------------------
// Kernel 0: build all weight fragments ONCE into device globals.
// ---------------------------------------------------------------------------
__global__ __launch_bounds__(256) void build_wfrags(
    const float* __restrict__ W1, const float* __restrict__ W2) {
  const int tab = blockIdx.y;
  const int i = blockIdx.x * 256 + threadIdx.x;
  const int count = (tab == 3) ? 1024 : 2048;
  if (i >= count) return;

  const int ln = i & 31;
  const int npw = (tab == 3) ? ((i >> 5) & 3) : ((i >> 5) & 7);
  const int ks = (tab == 3) ? (i >> 7) : (i >> 8);
  const int k0 = ks * 16 + (ln & 3) * 2;
  const int ng0 = (2 * npw) * 8 + (ln >> 2);
  const int ng1 = (2 * npw + 1) * 8 + (ln >> 2);

  uint4 hi, lo;
  if (tab == 3) build_bfrag(W2, 128, ng0, ng1, k0, &hi, &lo);
  else          build_bfrag(W1 + tab * 128, 384, ng0, ng1, k0, &hi, &lo);
  g_Wf_hi[tab][i] = hi;
  g_Wf_lo[tab][i] = lo;
}

// ---------------------------------------------------------------------------
// Kernel A (tensor): P[p][n][j] = sum_k x[n][k] * W1[j][p*128+k]
// ---------------------------------------------------------------------------
#define PP_AHI 0
#define PP_ALO (4 * 16 * AROW)             // 17408
#define PP_BHI (2 * 4 * 16 * AROW)         // 34816
#define PP_BLO (PP_BHI + 32768)            // 67584
#define PP_SMEM (PP_BLO + 32768)           // 100352

__global__ void __launch_bounds__(128, 2) precompute_P_tc(
    const float* __restrict__ x, int nodes) {
  extern __shared__ char smem[];
  const uint32_t sbase = smem_u32(smem);
  const int tid = threadIdx.x;
  const int wid = tid >> 5;
  const int lane = tid & 31;
  const int p = blockIdx.y;

  uint4* Bhi4 = (uint4*)(smem + PP_BHI);   // [ks][np][lane], np=0..7 (16 nf)
  uint4* Blo4 = (uint4*)(smem + PP_BLO);

  const int ntiles = (nodes + 15) >> 4;
  const int wt = blockIdx.x * 4 + wid;
  const bool active = (wt < ntiles);
  const int n0 = wt << 4;

  // ---- coalesced fragment copy from global (prebuilt) ----
  {
    const uint4* sh = g_Wf_hi[p];
    const uint4* sl = g_Wf_lo[p];
    for (int i = tid; i < 2048; i += 128) {
      Bhi4[i] = sh[i];
      Blo4[i] = sl[i];
    }
  }

  // ---- A split: 16 x-rows -> trunc hi/lo bf16 in AROW layout ----
  const int sub = lane & 7;
  const int rgl = lane >> 3;
  char* tile_hi = smem + PP_AHI + (size_t)wid * 16 * AROW;
  char* tile_lo = smem + PP_ALO + (size_t)wid * 16 * AROW;
  if (active) {
#pragma unroll
    for (int rg = 0; rg < 4; rg++) {
      const int r = rg * 4 + rgl;
      const int gr = min(n0 + r, nodes - 1);
      const float* xr = x + (size_t)gr * 128;
      char* rhi = tile_hi + (size_t)r * AROW;
      char* rlo = tile_lo + (size_t)r * AROW;
#pragma unroll
      for (int q = 0; q < 4; q++) {
        const int c = q * 32 + sub * 4;
        const float4 v4 = *(const float4*)(xr + c);
        const uint32_t hi01 = __byte_perm(__float_as_uint(v4.x),
                                          __float_as_uint(v4.y), 0x7632);
        const uint32_t hi23 = __byte_perm(__float_as_uint(v4.z),
                                          __float_as_uint(v4.w), 0x7632);
        const float l0 = v4.x - trunc_bf16(v4.x);
        const float l1 = v4.y - trunc_bf16(v4.y);
        const float l2 = v4.z - trunc_bf16(v4.z);
        const float l3 = v4.w - trunc_bf16(v4.w);
        const __nv_bfloat162 lp01 = __floats2bfloat162_rn(l0, l1);
        const __nv_bfloat162 lp23 = __floats2bfloat162_rn(l2, l3);
        const int qb = (q < 2) ? (q * 64 + sub * 8)
                               : (HALF_OFF + (q - 2) * 64 + sub * 8);
        *(uint2*)(rhi + qb) = make_uint2(hi01, hi23);
        *(uint2*)(rlo + qb) =
            make_uint2(*(const uint32_t*)&lp01, *(const uint32_t*)&lp23);
      }
    }
  }
  __syncthreads();

  if (!active) return;

  // ldmatrix addressing
  const uint32_t lrow = (lane < 16) ? lane : (lane - 16);
  const uint32_t lcol = (lane < 16) ? 0u : 16u;
  const uint32_t ahi_ld = sbase + PP_AHI + (wid * 16 + lrow) * AROW + lcol;
  const uint32_t alo_ld = sbase + PP_ALO + (wid * 16 + lrow) * AROW + lcol;

  float acc[16][4];
#pragma unroll
  for (int n = 0; n < 16; n++)
#pragma unroll
    for (int q = 0; q < 4; q++) acc[n][q] = 0.f;

#pragma unroll
  for (int ks = 0; ks < 8; ks++) {
    const uint32_t kb = ks * 32 + ((ks >= 4) ? 16u : 0u);
    uint32_t ah0, ah1, ah2, ah3, al0, al1, al2, al3;
    LDSM4(ah0, ah1, ah2, ah3, ahi_ld + kb);
    LDSM4(al0, al1, al2, al3, alo_ld + kb);
#pragma unroll
    for (int np = 0; np < 8; np++) {
      const uint4 vh = Bhi4[(ks * 8 + np) * 32 + lane];
      const uint4 vl = Blo4[(ks * 8 + np) * 32 + lane];
      MMA16816(acc[2 * np], ah0, ah1, ah2, ah3, vh.x, vh.y);
      MMA16816(acc[2 * np], ah0, ah1, ah2, ah3, vl.x, vl.y);
      MMA16816(acc[2 * np], al0, al1, al2, al3, vh.x, vh.y);
      MMA16816(acc[2 * np + 1], ah0, ah1, ah2, ah3, vh.z, vh.w);
      MMA16816(acc[2 * np + 1], ah0, ah1, ah2, ah3, vl.z, vl.w);
      MMA16816(acc[2 * np + 1], al0, al1, al2, al3, vh.z, vh.w);
    }
  }

  // store D -> g_P[p]
  float* Pp = g_P + (size_t)p * NCAP * 128;
  const int r0 = n0 + (lane >> 2);
  const int r1 = r0 + 8;
#pragma unroll
  for (int nf = 0; nf < 16; nf++) {
    const int c0 = nf * 8 + (lane & 3) * 2;
    if (r0 < nodes)
      *(float2*)(Pp + (size_t)r0 * 128 + c0) = make_float2(acc[nf][0], acc[nf][1]);
    if (r1 < nodes)
      *(float2*)(Pp + (size_t)r1 * 128 + c0) = make_float2(acc[nf][2], acc[nf][3]);
  }
}

// ---------------------------------------------------------------------------
// Kernel B: per-group context term (+ b1 folded in)
// ---------------------------------------------------------------------------
__global__ __launch_bounds__(128) void group_ctx(
    const int* __restrict__ indices, const float* __restrict__ b1, int G) {
  const int g = blockIdx.x;
  if (g >= G) return;
  const int t = threadIdx.x;
  const int* ip = indices + (size_t)g * 25 * 23 + 3;
  const float* Pc = g_P + (size_t)2 * NCAP * 128;

  float s = 0.f;
  int cnt = 0;
#pragma unroll
  for (int kk = 0; kk < 20; kk++) {
    const int id = ip[kk];
    s += Pc[(size_t)id * 128 + t];
    cnt += (id > 0) ? 1 : 0;
  }
  const float norm = (float)(cnt > 0 ? cnt : 1);
  g_Gc[(size_t)g * 128 + t] = s / norm + b1[t];
}

// ---------------------------------------------------------------------------
// Kernel C: pair-split HMMA MLP. 256 thr = 8 warps = 4 pairs.
// Pair owns a 32-row A tile (each warp gathers 16 rows, same as R11);
// warp-half h computes only channels 32h..32h+31 -> B re-reads halved while
// keeping 16 warps/SM. Cross-warp channel reduction via smem partials.
// ---------------------------------------------------------------------------
#define AHI_OFF 0
#define ALO_OFF (8 * 16 * AROW)        // 34816
#define BF_OFF (2 * (8 * 16 * AROW))   // 69632
#define BFRAG_U4 1024                  // (8 ks * 4 np * 32 lanes) uint4 per pass
#define MISC_OFF (BF_OFF + 2 * BFRAG_U4 * 16)  // 102400
#define SMEM_BYTES (MISC_OFF + 2816)   // b2s 256 + w3s 256 + pbuf 2048 + pad

__global__ void __launch_bounds__(256, 2) mlp_main_mma(
    const int* __restrict__ indices,
    const float* __restrict__ b2, const float* __restrict__ W3,
    const float* __restrict__ b3,
    float* __restrict__ out, int N) {
  extern __shared__ char smem[];
  const uint32_t sbase = smem_u32(smem);

  const int tid = threadIdx.x;
  const int wid = tid >> 5;
  const int lane = tid & 31;
  const int pair = wid >> 1;
  const int half = wid & 1;

  uint4* Bhi4 = (uint4*)(smem + BF_OFF);     // [ks][np][lane]
  uint4* Blo4 = Bhi4 + BFRAG_U4;
  float* b2s = (float*)(smem + MISC_OFF);
  float* w3s = b2s + 64;
  float* pbuf = b2s + 128;                   // [2 parity][4 pair][2 half][32]

  // ---- coalesced W2 fragment copy (prebuilt, table 3) ----
  {
    const uint4* sh = g_Wf_hi[3];
    const uint4* sl = g_Wf_lo[3];
    for (int i = tid; i < BFRAG_U4; i += 256) {
      Bhi4[i] = sh[i];
      Blo4[i] = sl[i];
    }
  }
  if (tid < 64) { b2s[tid] = b2[tid]; w3s[tid] = W3[tid]; }
  const float b3v = b3[0];
  __syncthreads();

  const float* Pa = g_P;
  const float* Pb = g_P + (size_t)NCAP * 128;

  const int sub = lane & 7;          // 16B sub-block within a 128B line
  const int rgl = lane >> 3;         // row within group of 4
  // gather target: this warp's 16 rows (rows wid*16 .. +15 of block tile)
  char* tile_hi = smem + AHI_OFF + (size_t)(wid * 16) * AROW;
  char* tile_lo = smem + ALO_OFF + (size_t)(wid * 16) * AROW;

  // ldmatrix base: the PAIR's 32 rows
  const uint32_t lrow = (lane < 16) ? lane : (lane - 16);
  const uint32_t lcol = (lane < 16) ? 0u : 16u;
  const uint32_t ahi_ld = sbase + AHI_OFF + (pair * 32 + lrow) * AROW + lcol;
  const uint32_t alo_ld = sbase + ALO_OFF + (pair * 32 + lrow) * AROW + lcol;

  const int NT32 = (N + 31) >> 5;    // 32-row pair tiles
  const int pstride = gridDim.x * 4;
  int par = 0;

  for (int wt = blockIdx.x * 4 + pair; wt < NT32; wt += pstride) {
    const int rbase = wt << 5;

    // ---- Phase A: this warp gathers its 16 rows (rbase + half*16 ..) ----
#pragma unroll
    for (int rg = 0; rg < 4; rg++) {
      const int r = rg * 4 + rgl;
      const int gr = min(rbase + half * 16 + r, N - 1);
      const int i0 = indices[(size_t)gr * 23 + 0];
      const int i1 = indices[(size_t)gr * 23 + 1];
      const int g = gr / 25;
      const float* pa = Pa + (size_t)i0 * 128;
      const float* pb = Pb + (size_t)i1 * 128;
      const float* gc = g_Gc + (size_t)g * 128;
      char* rhi = tile_hi + (size_t)r * AROW;
      char* rlo = tile_lo + (size_t)r * AROW;
#pragma unroll
      for (int q = 0; q < 4; q++) {
        const int c = q * 32 + sub * 4;
        const float4 va = *(const float4*)(pa + c);
        const float4 vb = *(const float4*)(pb + c);
        const float4 vg = *(const float4*)(gc + c);
        float v0 = fmaxf(va.x + vb.x + vg.x, 0.f);
        float v1 = fmaxf(va.y + vb.y + vg.y, 0.f);
        float v2 = fmaxf(va.z + vb.z + vg.z, 0.f);
        float v3 = fmaxf(va.w + vb.w + vg.w, 0.f);
        const uint32_t hi01 =
            __byte_perm(__float_as_uint(v0), __float_as_uint(v1), 0x7632);
        const uint32_t hi23 =
            __byte_perm(__float_as_uint(v2), __float_as_uint(v3), 0x7632);
        const float l0 = v0 - trunc_bf16(v0);
        const float l1 = v1 - trunc_bf16(v1);
        const float l2 = v2 - trunc_bf16(v2);
        const float l3 = v3 - trunc_bf16(v3);
        const __nv_bfloat162 lp01 = __floats2bfloat162_rn(l0, l1);
        const __nv_bfloat162 lp23 = __floats2bfloat162_rn(l2, l3);
        const int qb = (q < 2) ? (q * 64 + sub * 8)
                               : (HALF_OFF + (q - 2) * 64 + sub * 8);
        *(uint2*)(rhi + qb) = make_uint2(hi01, hi23);
        *(uint2*)(rlo + qb) =
            make_uint2(*(const uint32_t*)&lp01, *(const uint32_t*)&lp23);
      }
    }
    // pair barrier: both warps' A halves visible before MMA
    asm volatile("bar.sync %0, 64;" :: "r"(1 + pair) : "memory");

    // ---- Phase B: 3-pass HMMA, this warp's channel half only ----
    float acc[2][4][4];
#pragma unroll
    for (int t = 0; t < 2; t++)
#pragma unroll
      for (int n = 0; n < 4; n++)
#pragma unroll
        for (int q = 0; q < 4; q++) acc[t][n][q] = 0.f;

#pragma unroll
    for (int ks = 0; ks < 8; ks++) {
      const uint32_t kb = ks * 32 + ((ks >= 4) ? 16u : 0u);
      uint32_t a0h0, a0h1, a0h2, a0h3, a0l0, a0l1, a0l2, a0l3;
      uint32_t a1h0, a1h1, a1h2, a1h3, a1l0, a1l1, a1l2, a1l3;
      LDSM4(a0h0, a0h1, a0h2, a0h3, ahi_ld + kb);
      LDSM4(a0l0, a0l1, a0l2, a0l3, alo_ld + kb);
      LDSM4(a1h0, a1h1, a1h2, a1h3, ahi_ld + 16 * AROW + kb);
      LDSM4(a1l0, a1l1, a1l2, a1l3, alo_ld + 16 * AROW + kb);
#pragma unroll
      for (int npl = 0; npl < 2; npl++) {
        const int np = 2 * half + npl;
        const uint4 vh = Bhi4[(ks * 4 + np) * 32 + lane];
        const uint4 vl = Blo4[(ks * 4 + np) * 32 + lane];
        MMA16816(acc[0][2 * npl], a0h0, a0h1, a0h2, a0h3, vh.x, vh.y);
        MMA16816(acc[0][2 * npl], a0h0, a0h1, a0h2, a0h3, vl.x, vl.y);
        MMA16816(acc[0][2 * npl], a0l0, a0l1, a0l2, a0l3, vh.x, vh.y);
        MMA16816(acc[0][2 * npl + 1], a0h0, a0h1, a0h2, a0h3, vh.z, vh.w);
        MMA16816(acc[0][2 * npl + 1], a0h0, a0h1, a0h2, a0h3, vl.z, vl.w);
        MMA16816(acc[0][2 * npl + 1], a0l0, a0l1, a0l2, a0l3, vh.z, vh.w);
        MMA16816(acc[1][2 * npl], a1h0, a1h1, a1h2, a1h3, vh.x, vh.y);
        MMA16816(acc[1][2 * npl], a1h0, a1h1, a1h2, a1h3, vl.x, vl.y);
        MMA16816(acc[1][2 * npl], a1l0, a1l1, a1l2, a1l3, vh.x, vh.y);
        MMA16816(acc[1][2 * npl + 1], a1h0, a1h1, a1h2, a1h3, vh.z, vh.w);
        MMA16816(acc[1][2 * npl + 1], a1h0, a1h1, a1h2, a1h3, vl.z, vl.w);
        MMA16816(acc[1][2 * npl + 1], a1l0, a1l1, a1l2, a1l3, vh.z, vh.w);
      }
    }

    // ---- Epilogue: partial (32-channel) sums -> smem, pair-combine ----
    float* myp = pbuf + ((par * 4 + pair) * 2 + half) * 32;
#pragma unroll
    for (int t = 0; t < 2; t++) {
      float s0 = 0.f, s1 = 0.f;
#pragma unroll
      for (int n = 0; n < 4; n++) {
        const int c0 = (4 * half + n) * 8 + (lane & 3) * 2;
        const float2 b2p = *(const float2*)(b2s + c0);
        const float2 w3p = *(const float2*)(w3s + c0);
        s0 = fmaf(fmaxf(acc[t][n][0] + b2p.x, 0.f), w3p.x, s0);
        s0 = fmaf(fmaxf(acc[t][n][1] + b2p.y, 0.f), w3p.y, s0);
        s1 = fmaf(fmaxf(acc[t][n][2] + b2p.x, 0.f), w3p.x, s1);
        s1 = fmaf(fmaxf(acc[t][n][3] + b2p.y, 0.f), w3p.y, s1);
      }
      s0 += __shfl_xor_sync(0xffffffffu, s0, 1);
      s0 += __shfl_xor_sync(0xffffffffu, s0, 2);
      s1 += __shfl_xor_sync(0xffffffffu, s1, 1);
      s1 += __shfl_xor_sync(0xffffffffu, s1, 2);
      if ((lane & 3) == 0) {
        myp[t * 16 + (lane >> 2)] = s0;
        myp[t * 16 + 8 + (lane >> 2)] = s1;
      }
    }
    asm volatile("bar.sync %0, 64;" :: "r"(1 + pair) : "memory");
    if (half == 0) {
      const float* p0 = pbuf + ((par * 4 + pair) * 2) * 32;
      const int r = rbase + lane;
      if (r < N) out[r] = p0[lane] + p0[32 + lane] + b3v;
    }
    par ^= 1;
  }
}

// ---------------------------------------------------------------------------
extern "C" void kernel_launch(void* const* d_in, const int* in_sizes, int n_in,
                              void* d_out, int out_size) {
  const int* indices = (const int*)d_in[0];
  // d_in[1] = nr (fixed 24)
  const float* x  = (const float*)d_in[2];
  const float* W1 = (const float*)d_in[3];
  const float* b1 = (const float*)d_in[4];
  const float* W2 = (const float*)d_in[5];
  const float* b2 = (const float*)d_in[6];
  const float* W3 = (const float*)d_in[7];
  const float* b3 = (const float*)d_in[8];
  float* out = (float*)d_out;

  const int N = in_sizes[0] / 23;          // 500000
  const int nodes = in_sizes[2] / 128;     // 10000
  const int G = (N - 2) / 25 + 1;          // 20000 groups
  const int ntiles = (nodes + 15) / 16;    // 625

  cudaFuncSetAttribute(precompute_P_tc,
                       cudaFuncAttributeMaxDynamicSharedMemorySize, PP_SMEM);
  cudaFuncSetAttribute(mlp_main_mma,
                       cudaFuncAttributeMaxDynamicSharedMemorySize, SMEM_BYTES);

  dim3 gridW(8, 4);
  build_wfrags<<<gridW, 256>>>(W1, W2);
  dim3 gridP((ntiles + 3) / 4, 3);
  precompute_P_tc<<<gridP, 128, PP_SMEM>>>(x, nodes);
  group_ctx<<<G, 128>>>(indices, b1, G);
  mlp_main_mma<<<296, 256, SMEM_BYTES>>>(indices, b2, W3, b3, out, N);
}

// round 14
// speedup vs baseline: 1.1664x; 1.1283x over previous
#include <cuda_runtime.h>
#include <cuda_bf16.h>
#include <cuda_fp16.h>
#include <cstdint>

#define NCAP 10240            // node capacity for P tables
#define GCAP 20032            // group capacity

// Scratch (device globals: no allocations allowed). P/Gc in fp16.
__device__ __half g_Ph[3 * NCAP * 128];  // Pa | Pb | Pc
__device__ __half g_Gch[GCAP * 128];     // per-group ctx term (+ b1 folded)

// Prebuilt weight fragments: tables 0..2 = W1 parts (2048 u4), 3 = W2 (1024 u4)
__device__ uint4 g_Wf_hi[4][2048];
__device__ uint4 g_Wf_lo[4][2048];

// ---------------------------------------------------------------------------
// helpers
// ---------------------------------------------------------------------------
__device__ __forceinline__ uint32_t smem_u32(const void* p) {
  uint32_t a;
  asm("{ .reg .u64 t; cvta.to.shared.u64 t, %1; cvt.u32.u64 %0, t; }"
      : "=r"(a) : "l"(p));
  return a;
}

__device__ __forceinline__ uint32_t bpack(__nv_bfloat16 a, __nv_bfloat16 b) {
  __nv_bfloat162 t(a, b);          // .x = a (low half)
  return *reinterpret_cast<uint32_t*>(&t);
}

#define LDSM4(r0, r1, r2, r3, addr)                                          \
  asm volatile(                                                              \
      "ldmatrix.sync.aligned.m8n8.x4.shared.b16 {%0,%1,%2,%3}, [%4];"        \
      : "=r"(r0), "=r"(r1), "=r"(r2), "=r"(r3) : "r"(addr))

#define MMA16816(d, a0, a1, a2, a3, b0, b1)                                  \
  asm volatile(                                                              \
      "mma.sync.aligned.m16n8k16.row.col.f32.bf16.bf16.f32 "                 \
      "{%0,%1,%2,%3}, {%4,%5,%6,%7}, {%8,%9}, {%0,%1,%2,%3};"                \
      : "+f"((d)[0]), "+f"((d)[1]), "+f"((d)[2]), "+f"((d)[3])               \
      : "r"(a0), "r"(a1), "r"(a2), "r"(a3), "r"(b0), "r"(b1))

// truncate fp32 to bf16 (toward zero); exact residual in fp32
__device__ __forceinline__ float trunc_bf16(float v) {
  return __uint_as_float(__float_as_uint(v) & 0xffff0000u);
}

// Common A-tile geometry (shared by both MMA kernels)
#define AROW 272                       // bytes per 128-ch row (16-aligned halves)
#define HALF_OFF 144                   // byte offset of channels 64..127

// build one hi/lo B-fragment uint4 pair from two weight rows
__device__ __forceinline__ void build_bfrag(const float* w_base, int row_stride,
                                            int ng0, int ng1, int k0,
                                            uint4* hi, uint4* lo) {
  uint32_t hx[2], hy[2], lx[2], ly[2];
  const int ngs[2] = {ng0, ng1};
#pragma unroll
  for (int t = 0; t < 2; t++) {
    const float* wr = w_base + (size_t)ngs[t] * row_stride + k0;
    const float w00 = wr[0], w01 = wr[1], w10 = wr[8], w11 = wr[9];
    __nv_bfloat16 h00 = __float2bfloat16(w00);
    __nv_bfloat16 h01 = __float2bfloat16(w01);
    __nv_bfloat16 h10 = __float2bfloat16(w10);
    __nv_bfloat16 h11 = __float2bfloat16(w11);
    __nv_bfloat16 l00 = __float2bfloat16(w00 - __bfloat162float(h00));
    __nv_bfloat16 l01 = __float2bfloat16(w01 - __bfloat162float(h01));
    __nv_bfloat16 l10 = __float2bfloat16(w10 - __bfloat162float(h10));
    __nv_bfloat16 l11 = __float2bfloat16(w11 - __bfloat162float(h11));
    hx[t] = bpack(h00, h01); hy[t] = bpack(h10, h11);
    lx[t] = bpack(l00, l01); ly[t] = bpack(l10, l11);
  }
  *hi = make_uint4(hx[0], hy[0], hx[1], hy[1]);
  *lo = make_uint4(lx[0], ly[0], lx[1], ly[1]);
}

// ---------------------------------------------------------------------------
// Kernel 0: build all weight fragments ONCE into device globals.
// ---------------------------------------------------------------------------
__global__ __launch_bounds__(256) void build_wfrags(
    const float* __restrict__ W1, const float* __restrict__ W2) {
  const int tab = blockIdx.y;
  const int i = blockIdx.x * 256 + threadIdx.x;
  const int count = (tab == 3) ? 1024 : 2048;
  if (i >= count) return;

  const int ln = i & 31;
  const int npw = (tab == 3) ? ((i >> 5) & 3) : ((i >> 5) & 7);
  const int ks = (tab == 3) ? (i >> 7) : (i >> 8);
  const int k0 = ks * 16 + (ln & 3) * 2;
  const int ng0 = (2 * npw) * 8 + (ln >> 2);
  const int ng1 = (2 * npw + 1) * 8 + (ln >> 2);

  uint4 hi, lo;
  if (tab == 3) build_bfrag(W2, 128, ng0, ng1, k0, &hi, &lo);
  else          build_bfrag(W1 + tab * 128, 384, ng0, ng1, k0, &hi, &lo);
  g_Wf_hi[tab][i] = hi;
  g_Wf_lo[tab][i] = lo;
}

// ---------------------------------------------------------------------------
// Kernel A (tensor): P[p][n][j] = sum_k x[n][k] * W1[j][p*128+k], fp16 out
// ---------------------------------------------------------------------------
#define PP_AHI 0
#define PP_ALO (4 * 16 * AROW)             // 17408
#define PP_BHI (2 * 4 * 16 * AROW)         // 34816
#define PP_BLO (PP_BHI + 32768)            // 67584
#define PP_SMEM (PP_BLO + 32768)           // 100352

__global__ void __launch_bounds__(128, 2) precompute_P_tc(
    const float* __restrict__ x, int nodes) {
  extern __shared__ char smem[];
  const uint32_t sbase = smem_u32(smem);
  const int tid = threadIdx.x;
  const int wid = tid >> 5;
  const int lane = tid & 31;
  const int p = blockIdx.y;

  uint4* Bhi4 = (uint4*)(smem + PP_BHI);   // [ks][np][lane], np=0..7 (16 nf)
  uint4* Blo4 = (uint4*)(smem + PP_BLO);

  const int ntiles = (nodes + 15) >> 4;
  const int wt = blockIdx.x * 4 + wid;
  const bool active = (wt < ntiles);
  const int n0 = wt << 4;

  // ---- coalesced fragment copy from global (prebuilt) ----
  {
    const uint4* sh = g_Wf_hi[p];
    const uint4* sl = g_Wf_lo[p];
    for (int i = tid; i < 2048; i += 128) {
      Bhi4[i] = sh[i];
      Blo4[i] = sl[i];
    }
  }

  // ---- A split: 16 x-rows -> trunc hi/lo bf16 in AROW layout ----
  const int sub = lane & 7;
  const int rgl = lane >> 3;
  char* tile_hi = smem + PP_AHI + (size_t)wid * 16 * AROW;
  char* tile_lo = smem + PP_ALO + (size_t)wid * 16 * AROW;
  if (active) {
#pragma unroll
    for (int rg = 0; rg < 4; rg++) {
      const int r = rg * 4 + rgl;
      const int gr = min(n0 + r, nodes - 1);
      const float* xr = x + (size_t)gr * 128;
      char* rhi = tile_hi + (size_t)r * AROW;
      char* rlo = tile_lo + (size_t)r * AROW;
#pragma unroll
      for (int q = 0; q < 4; q++) {
        const int c = q * 32 + sub * 4;
        const float4 v4 = *(const float4*)(xr + c);
        const uint32_t hi01 = __byte_perm(__float_as_uint(v4.x),
                                          __float_as_uint(v4.y), 0x7632);
        const uint32_t hi23 = __byte_perm(__float_as_uint(v4.z),
                                          __float_as_uint(v4.w), 0x7632);
        const float l0 = v4.x - trunc_bf16(v4.x);
        const float l1 = v4.y - trunc_bf16(v4.y);
        const float l2 = v4.z - trunc_bf16(v4.z);
        const float l3 = v4.w - trunc_bf16(v4.w);
        const __nv_bfloat162 lp01 = __floats2bfloat162_rn(l0, l1);
        const __nv_bfloat162 lp23 = __floats2bfloat162_rn(l2, l3);
        const int qb = (q < 2) ? (q * 64 + sub * 8)
                               : (HALF_OFF + (q - 2) * 64 + sub * 8);
        *(uint2*)(rhi + qb) = make_uint2(hi01, hi23);
        *(uint2*)(rlo + qb) =
            make_uint2(*(const uint32_t*)&lp01, *(const uint32_t*)&lp23);
      }
    }
  }
  __syncthreads();

  if (!active) return;

  // ldmatrix addressing
  const uint32_t lrow = (lane < 16) ? lane : (lane - 16);
  const uint32_t lcol = (lane < 16) ? 0u : 16u;
  const uint32_t ahi_ld = sbase + PP_AHI + (wid * 16 + lrow) * AROW + lcol;
  const uint32_t alo_ld = sbase + PP_ALO + (wid * 16 + lrow) * AROW + lcol;

  float acc[16][4];
#pragma unroll
  for (int n = 0; n < 16; n++)
#pragma unroll
    for (int q = 0; q < 4; q++) acc[n][q] = 0.f;

#pragma unroll
  for (int ks = 0; ks < 8; ks++) {
    const uint32_t kb = ks * 32 + ((ks >= 4) ? 16u : 0u);
    uint32_t ah0, ah1, ah2, ah3, al0, al1, al2, al3;
    LDSM4(ah0, ah1, ah2, ah3, ahi_ld + kb);
    LDSM4(al0, al1, al2, al3, alo_ld + kb);
#pragma unroll
    for (int np = 0; np < 8; np++) {
      const uint4 vh = Bhi4[(ks * 8 + np) * 32 + lane];
      const uint4 vl = Blo4[(ks * 8 + np) * 32 + lane];
      MMA16816(acc[2 * np], ah0, ah1, ah2, ah3, vh.x, vh.y);
      MMA16816(acc[2 * np], ah0, ah1, ah2, ah3, vl.x, vl.y);
      MMA16816(acc[2 * np], al0, al1, al2, al3, vh.x, vh.y);
      MMA16816(acc[2 * np + 1], ah0, ah1, ah2, ah3, vh.z, vh.w);
      MMA16816(acc[2 * np + 1], ah0, ah1, ah2, ah3, vl.z, vl.w);
      MMA16816(acc[2 * np + 1], al0, al1, al2, al3, vh.z, vh.w);
    }
  }

  // store D -> g_Ph[p] as fp16 pairs
  __half* Pp = g_Ph + (size_t)p * NCAP * 128;
  const int r0 = n0 + (lane >> 2);
  const int r1 = r0 + 8;
#pragma unroll
  for (int nf = 0; nf < 16; nf++) {
    const int c0 = nf * 8 + (lane & 3) * 2;
    if (r0 < nodes)
      *(__half2*)(Pp + (size_t)r0 * 128 + c0) =
          __floats2half2_rn(acc[nf][0], acc[nf][1]);
    if (r1 < nodes)
      *(__half2*)(Pp + (size_t)r1 * 128 + c0) =
          __floats2half2_rn(acc[nf][2], acc[nf][3]);
  }
}

// ---------------------------------------------------------------------------
// Kernel B: per-group context term (+ b1 folded in), fp16 in/out
// ---------------------------------------------------------------------------
__global__ __launch_bounds__(128) void group_ctx(
    const int* __restrict__ indices, const float* __restrict__ b1, int G) {
  const int g = blockIdx.x;
  if (g >= G) return;
  const int t = threadIdx.x;
  const int* ip = indices + (size_t)g * 25 * 23 + 3;
  const __half* Pc = g_Ph + (size_t)2 * NCAP * 128;

  float s = 0.f;
  int cnt = 0;
#pragma unroll
  for (int kk = 0; kk < 20; kk++) {
    const int id = ip[kk];
    s += __half2float(Pc[(size_t)id * 128 + t]);
    cnt += (id > 0) ? 1 : 0;
  }
  const float norm = (float)(cnt > 0 ? cnt : 1);
  g_Gch[(size_t)g * 128 + t] = __float2half(s / norm + b1[t]);
}

// ---------------------------------------------------------------------------
// Kernel C: warp-independent HMMA MLP (R11 structure). Each warp owns a
// 16-row tile. fp16 gathers (half the bytes of fp32).
// ---------------------------------------------------------------------------
#define AHI_OFF 0
#define ALO_OFF (8 * 16 * AROW)        // 34816
#define BF_OFF (2 * (8 * 16 * AROW))   // 69632
#define BFRAG_U4 1024                  // (8 ks * 4 np * 32 lanes) uint4 per pass
#define MISC_OFF (BF_OFF + 2 * BFRAG_U4 * 16)  // 102400
#define SMEM_BYTES (MISC_OFF + 768)

__global__ void __launch_bounds__(256, 2) mlp_main_mma(
    const int* __restrict__ indices,
    const float* __restrict__ b2, const float* __restrict__ W3,
    const float* __restrict__ b3,
    float* __restrict__ out, int N) {
  extern __shared__ char smem[];
  const uint32_t sbase = smem_u32(smem);

  const int tid = threadIdx.x;
  const int wid = tid >> 5;
  const int lane = tid & 31;

  uint4* Bhi4 = (uint4*)(smem + BF_OFF);     // [ks][np][lane]
  uint4* Blo4 = Bhi4 + BFRAG_U4;
  float* b2s = (float*)(smem + MISC_OFF);
  float* w3s = b2s + 64;

  // ---- coalesced W2 fragment copy (prebuilt, table 3) ----
  {
    const uint4* sh = g_Wf_hi[3];
    const uint4* sl = g_Wf_lo[3];
    for (int i = tid; i < BFRAG_U4; i += 256) {
      Bhi4[i] = sh[i];
      Blo4[i] = sl[i];
    }
  }
  if (tid < 64) { b2s[tid] = b2[tid]; w3s[tid] = W3[tid]; }
  const float b3v = b3[0];
  __syncthreads();

  const char* PaB = (const char*)g_Ph;
  const char* PbB = (const char*)(g_Ph + (size_t)NCAP * 128);
  const char* GcB = (const char*)g_Gch;

  const int sub = lane & 7;          // 16B sub-block (8 fp16 ch) within a row
  const int rgl = lane >> 3;         // row within group of 4
  char* tile_hi = smem + AHI_OFF + (size_t)(wid * 16) * AROW;
  char* tile_lo = smem + ALO_OFF + (size_t)(wid * 16) * AROW;

  const uint32_t lrow = (lane < 16) ? lane : (lane - 16);
  const uint32_t lcol = (lane < 16) ? 0u : 16u;
  const uint32_t ahi_ld = sbase + AHI_OFF + (wid * 16 + lrow) * AROW + lcol;
  const uint32_t alo_ld = sbase + ALO_OFF + (wid * 16 + lrow) * AROW + lcol;

  const int NTW = (N + 15) >> 4;
  const int wstride = gridDim.x * 8;

  for (int wt = blockIdx.x * 8 + wid; wt < NTW; wt += wstride) {
    const int rbase = wt << 4;

    // ---- Phase A: fp16 gather + relu + truncation bf16 hi/lo split ----
#pragma unroll
    for (int rg = 0; rg < 4; rg++) {
      const int r = rg * 4 + rgl;
      const int gr = min(rbase + r, N - 1);
      const int i0 = indices[(size_t)gr * 23 + 0];
      const int i1 = indices[(size_t)gr * 23 + 1];
      const int g = gr / 25;
      const char* pa = PaB + (size_t)i0 * 256;
      const char* pb = PbB + (size_t)i1 * 256;
      const char* gc = GcB + (size_t)g * 256;
      char* rhi = tile_hi + (size_t)r * AROW;
      char* rlo = tile_lo + (size_t)r * AROW;
#pragma unroll
      for (int q = 0; q < 2; q++) {
        const int off = q * 128 + sub * 16;   // 8 fp16 channels
        const uint4 ua = *(const uint4*)(pa + off);
        const uint4 ub = *(const uint4*)(pb + off);
        const uint4 ug = *(const uint4*)(gc + off);
        const __half2* ha = (const __half2*)&ua;
        const __half2* hb = (const __half2*)&ub;
        const __half2* hg = (const __half2*)&ug;
        float v[8];
#pragma unroll
        for (int j = 0; j < 4; j++) {
          const float2 fa = __half22float2(ha[j]);
          const float2 fb = __half22float2(hb[j]);
          const float2 fg = __half22float2(hg[j]);
          v[2 * j]     = fmaxf(fa.x + fb.x + fg.x, 0.f);
          v[2 * j + 1] = fmaxf(fa.y + fb.y + fg.y, 0.f);
        }
        const uint32_t hi01 =
            __byte_perm(__float_as_uint(v[0]), __float_as_uint(v[1]), 0x7632);
        const uint32_t hi23 =
            __byte_perm(__float_as_uint(v[2]), __float_as_uint(v[3]), 0x7632);
        const uint32_t hi45 =
            __byte_perm(__float_as_uint(v[4]), __float_as_uint(v[5]), 0x7632);
        const uint32_t hi67 =
            __byte_perm(__float_as_uint(v[6]), __float_as_uint(v[7]), 0x7632);
        float l[8];
#pragma unroll
        for (int j = 0; j < 8; j++) l[j] = v[j] - trunc_bf16(v[j]);
        const __nv_bfloat162 lp01 = __floats2bfloat162_rn(l[0], l[1]);
        const __nv_bfloat162 lp23 = __floats2bfloat162_rn(l[2], l[3]);
        const __nv_bfloat162 lp45 = __floats2bfloat162_rn(l[4], l[5]);
        const __nv_bfloat162 lp67 = __floats2bfloat162_rn(l[6], l[7]);
        const int qb = (q == 0) ? (sub * 16) : (HALF_OFF + sub * 16);
        *(uint4*)(rhi + qb) = make_uint4(hi01, hi23, hi45, hi67);
        *(uint4*)(rlo + qb) =
            make_uint4(*(const uint32_t*)&lp01, *(const uint32_t*)&lp23,
                       *(const uint32_t*)&lp45, *(const uint32_t*)&lp67);
      }
    }
    __syncwarp();

    // ---- Phase B: 3-pass HMMA ----
    float acc[8][4];
#pragma unroll
    for (int n = 0; n < 8; n++)
#pragma unroll
      for (int q = 0; q < 4; q++) acc[n][q] = 0.f;

#pragma unroll
    for (int ks = 0; ks < 8; ks++) {
      const uint32_t kb = ks * 32 + ((ks >= 4) ? 16u : 0u);
      uint32_t ah0, ah1, ah2, ah3, al0, al1, al2, al3;
      LDSM4(ah0, ah1, ah2, ah3, ahi_ld + kb);
      LDSM4(al0, al1, al2, al3, alo_ld + kb);
#pragma unroll
      for (int np = 0; np < 4; np++) {
        const uint4 vh = Bhi4[(ks * 4 + np) * 32 + lane];
        const uint4 vl = Blo4[(ks * 4 + np) * 32 + lane];
        MMA16816(acc[2 * np], ah0, ah1, ah2, ah3, vh.x, vh.y);
        MMA16816(acc[2 * np], ah0, ah1, ah2, ah3, vl.x, vl.y);
        MMA16816(acc[2 * np], al0, al1, al2, al3, vh.x, vh.y);
        MMA16816(acc[2 * np + 1], ah0, ah1, ah2, ah3, vh.z, vh.w);
        MMA16816(acc[2 * np + 1], ah0, ah1, ah2, ah3, vl.z, vl.w);
        MMA16816(acc[2 * np + 1], al0, al1, al2, al3, vh.z, vh.w);
      }
    }

    // ---- Epilogue ----
    float s0 = 0.f, s1 = 0.f;
#pragma unroll
    for (int n = 0; n < 8; n++) {
      const int c0 = n * 8 + (lane & 3) * 2;
      const float2 b2p = *(const float2*)(b2s + c0);
      const float2 w3p = *(const float2*)(w3s + c0);
      s0 = fmaf(fmaxf(acc[n][0] + b2p.x, 0.f), w3p.x, s0);
      s0 = fmaf(fmaxf(acc[n][1] + b2p.y, 0.f), w3p.y, s0);
      s1 = fmaf(fmaxf(acc[n][2] + b2p.x, 0.f), w3p.x, s1);
      s1 = fmaf(fmaxf(acc[n][3] + b2p.y, 0.f), w3p.y, s1);
    }
    s0 += __shfl_xor_sync(0xffffffffu, s0, 1);
    s0 += __shfl_xor_sync(0xffffffffu, s0, 2);
    s1 += __shfl_xor_sync(0xffffffffu, s1, 1);
    s1 += __shfl_xor_sync(0xffffffffu, s1, 2);
    if ((lane & 3) == 0) {
      const int r0 = rbase + (lane >> 2);
      if (r0 < N) out[r0] = s0 + b3v;
      const int r1 = r0 + 8;
      if (r1 < N) out[r1] = s1 + b3v;
    }
    __syncwarp();   // protect smem tile reuse next iteration
  }
}

// ---------------------------------------------------------------------------
extern "C" void kernel_launch(void* const* d_in, const int* in_sizes, int n_in,
                              void* d_out, int out_size) {
  const int* indices = (const int*)d_in[0];
  // d_in[1] = nr (fixed 24)
  const float* x  = (const float*)d_in[2];
  const float* W1 = (const float*)d_in[3];
  const float* b1 = (const float*)d_in[4];
  const float* W2 = (const float*)d_in[5];
  const float* b2 = (const float*)d_in[6];
  const float* W3 = (const float*)d_in[7];
  const float* b3 = (const float*)d_in[8];
  float* out = (float*)d_out;

  const int N = in_sizes[0] / 23;          // 500000
  const int nodes = in_sizes[2] / 128;     // 10000
  const int G = (N - 2) / 25 + 1;          // 20000 groups
  const int ntiles = (nodes + 15) / 16;    // 625

  cudaFuncSetAttribute(precompute_P_tc,
                       cudaFuncAttributeMaxDynamicSharedMemorySize, PP_SMEM);
  cudaFuncSetAttribute(mlp_main_mma,
                       cudaFuncAttributeMaxDynamicSharedMemorySize, SMEM_BYTES);

  dim3 gridW(8, 4);
  build_wfrags<<<gridW, 256>>>(W1, W2);
  dim3 gridP((ntiles + 3) / 4, 3);
  precompute_P_tc<<<gridP, 128, PP_SMEM>>>(x, nodes);
  group_ctx<<<G, 128>>>(indices, b1, G);
  mlp_main_mma<<<296, 256, SMEM_BYTES>>>(indices, b2, W3, b3, out, N);
}

// round 15
// speedup vs baseline: 1.5252x; 1.3077x over previous
#include <cuda_runtime.h>
#include <cuda_bf16.h>
#include <cuda_fp16.h>
#include <cstdint>

#define NCAP 10240            // node capacity for P tables
#define GCAP 20032            // group capacity

// Scratch (device globals: no allocations allowed). P/Gc in fp16.
__device__ __half g_Ph[3 * NCAP * 128];  // Pa | Pb | Pc
__device__ __half g_Gch[GCAP * 128];     // per-group ctx term (+ b1 folded)

// Prebuilt weight fragments:
//  tables 0..2 = W1 parts, bf16 hi/lo (2048 u4 each) for 3-pass precompute
//  table  3    = W2, fp16 single-pass (1024 u4, hi only)
__device__ uint4 g_Wf_hi[4][2048];
__device__ uint4 g_Wf_lo[4][2048];

// ---------------------------------------------------------------------------
// helpers
// ---------------------------------------------------------------------------
__device__ __forceinline__ uint32_t smem_u32(const void* p) {
  uint32_t a;
  asm("{ .reg .u64 t; cvta.to.shared.u64 t, %1; cvt.u32.u64 %0, t; }"
      : "=r"(a) : "l"(p));
  return a;
}

__device__ __forceinline__ uint32_t bpack(__nv_bfloat16 a, __nv_bfloat16 b) {
  __nv_bfloat162 t(a, b);          // .x = a (low half)
  return *reinterpret_cast<uint32_t*>(&t);
}

__device__ __forceinline__ uint32_t hpack(float a, float b) {
  __half2 t = __floats2half2_rn(a, b);
  return *reinterpret_cast<uint32_t*>(&t);
}

#define LDSM4(r0, r1, r2, r3, addr)                                          \
  asm volatile(                                                              \
      "ldmatrix.sync.aligned.m8n8.x4.shared.b16 {%0,%1,%2,%3}, [%4];"        \
      : "=r"(r0), "=r"(r1), "=r"(r2), "=r"(r3) : "r"(addr))

#define MMA16816(d, a0, a1, a2, a3, b0, b1)                                  \
  asm volatile(                                                              \
      "mma.sync.aligned.m16n8k16.row.col.f32.bf16.bf16.f32 "                 \
      "{%0,%1,%2,%3}, {%4,%5,%6,%7}, {%8,%9}, {%0,%1,%2,%3};"                \
      : "+f"((d)[0]), "+f"((d)[1]), "+f"((d)[2]), "+f"((d)[3])               \
      : "r"(a0), "r"(a1), "r"(a2), "r"(a3), "r"(b0), "r"(b1))

#define MMA16816H(d, a0, a1, a2, a3, b0, b1)                                 \
  asm volatile(                                                              \
      "mma.sync.aligned.m16n8k16.row.col.f32.f16.f16.f32 "                   \
      "{%0,%1,%2,%3}, {%4,%5,%6,%7}, {%8,%9}, {%0,%1,%2,%3};"                \
      : "+f"((d)[0]), "+f"((d)[1]), "+f"((d)[2]), "+f"((d)[3])               \
      : "r"(a0), "r"(a1), "r"(a2), "r"(a3), "r"(b0), "r"(b1))

// truncate fp32 to bf16 (toward zero); exact residual in fp32
__device__ __forceinline__ float trunc_bf16(float v) {
  return __uint_as_float(__float_as_uint(v) & 0xffff0000u);
}

// Common A-tile geometry (shared by both MMA kernels)
#define AROW 272                       // bytes per 128-ch row (16-aligned halves)
#define HALF_OFF 144                   // byte offset of channels 64..127

// build one hi/lo bf16 B-fragment uint4 pair from two weight rows
__device__ __forceinline__ void build_bfrag(const float* w_base, int row_stride,
                                            int ng0, int ng1, int k0,
                                            uint4* hi, uint4* lo) {
  uint32_t hx[2], hy[2], lx[2], ly[2];
  const int ngs[2] = {ng0, ng1};
#pragma unroll
  for (int t = 0; t < 2; t++) {
    const float* wr = w_base + (size_t)ngs[t] * row_stride + k0;
    const float w00 = wr[0], w01 = wr[1], w10 = wr[8], w11 = wr[9];
    __nv_bfloat16 h00 = __float2bfloat16(w00);
    __nv_bfloat16 h01 = __float2bfloat16(w01);
    __nv_bfloat16 h10 = __float2bfloat16(w10);
    __nv_bfloat16 h11 = __float2bfloat16(w11);
    __nv_bfloat16 l00 = __float2bfloat16(w00 - __bfloat162float(h00));
    __nv_bfloat16 l01 = __float2bfloat16(w01 - __bfloat162float(h01));
    __nv_bfloat16 l10 = __float2bfloat16(w10 - __bfloat162float(h10));
    __nv_bfloat16 l11 = __float2bfloat16(w11 - __bfloat162float(h11));
    hx[t] = bpack(h00, h01); hy[t] = bpack(h10, h11);
    lx[t] = bpack(l00, l01); ly[t] = bpack(l10, l11);
  }
  *hi = make_uint4(hx[0], hy[0], hx[1], hy[1]);
  *lo = make_uint4(lx[0], ly[0], lx[1], ly[1]);
}

// ---------------------------------------------------------------------------
// Kernel 0: build all weight fragments ONCE into device globals.
// ---------------------------------------------------------------------------
__global__ __launch_bounds__(256) void build_wfrags(
    const float* __restrict__ W1, const float* __restrict__ W2) {
  const int tab = blockIdx.y;
  const int i = blockIdx.x * 256 + threadIdx.x;
  const int count = (tab == 3) ? 1024 : 2048;
  if (i >= count) return;

  const int ln = i & 31;
  const int npw = (tab == 3) ? ((i >> 5) & 3) : ((i >> 5) & 7);
  const int ks = (tab == 3) ? (i >> 7) : (i >> 8);
  const int k0 = ks * 16 + (ln & 3) * 2;
  const int ng0 = (2 * npw) * 8 + (ln >> 2);
  const int ng1 = (2 * npw + 1) * 8 + (ln >> 2);

  if (tab == 3) {
    // W2 as fp16 single-pass fragments
    uint32_t hx[2], hy[2];
    const int ngs[2] = {ng0, ng1};
#pragma unroll
    for (int t = 0; t < 2; t++) {
      const float* wr = W2 + (size_t)ngs[t] * 128 + k0;
      hx[t] = hpack(wr[0], wr[1]);
      hy[t] = hpack(wr[8], wr[9]);
    }
    g_Wf_hi[3][i] = make_uint4(hx[0], hy[0], hx[1], hy[1]);
  } else {
    uint4 hi, lo;
    build_bfrag(W1 + tab * 128, 384, ng0, ng1, k0, &hi, &lo);
    g_Wf_hi[tab][i] = hi;
    g_Wf_lo[tab][i] = lo;
  }
}

// ---------------------------------------------------------------------------
// Kernel A (tensor): P[p][n][j] = sum_k x[n][k] * W1[j][p*128+k], fp16 out
// bf16 3-pass split retained here (x is fp32; P quality feeds everything).
// ---------------------------------------------------------------------------
#define PP_AHI 0
#define PP_ALO (4 * 16 * AROW)             // 17408
#define PP_BHI (2 * 4 * 16 * AROW)         // 34816
#define PP_BLO (PP_BHI + 32768)            // 67584
#define PP_SMEM (PP_BLO + 32768)           // 100352

__global__ void __launch_bounds__(128, 2) precompute_P_tc(
    const float* __restrict__ x, int nodes) {
  extern __shared__ char smem[];
  const uint32_t sbase = smem_u32(smem);
  const int tid = threadIdx.x;
  const int wid = tid >> 5;
  const int lane = tid & 31;
  const int p = blockIdx.y;

  uint4* Bhi4 = (uint4*)(smem + PP_BHI);   // [ks][np][lane], np=0..7 (16 nf)
  uint4* Blo4 = (uint4*)(smem + PP_BLO);

  const int ntiles = (nodes + 15) >> 4;
  const int wt = blockIdx.x * 4 + wid;
  const bool active = (wt < ntiles);
  const int n0 = wt << 4;

  // ---- coalesced fragment copy from global (prebuilt) ----
  {
    const uint4* sh = g_Wf_hi[p];
    const uint4* sl = g_Wf_lo[p];
    for (int i = tid; i < 2048; i += 128) {
      Bhi4[i] = sh[i];
      Blo4[i] = sl[i];
    }
  }

  // ---- A split: 16 x-rows -> trunc hi/lo bf16 in AROW layout ----
  const int sub = lane & 7;
  const int rgl = lane >> 3;
  char* tile_hi = smem + PP_AHI + (size_t)wid * 16 * AROW;
  char* tile_lo = smem + PP_ALO + (size_t)wid * 16 * AROW;
  if (active) {
#pragma unroll
    for (int rg = 0; rg < 4; rg++) {
      const int r = rg * 4 + rgl;
      const int gr = min(n0 + r, nodes - 1);
      const float* xr = x + (size_t)gr * 128;
      char* rhi = tile_hi + (size_t)r * AROW;
      char* rlo = tile_lo + (size_t)r * AROW;
#pragma unroll
      for (int q = 0; q < 4; q++) {
        const int c = q * 32 + sub * 4;
        const float4 v4 = *(const float4*)(xr + c);
        const uint32_t hi01 = __byte_perm(__float_as_uint(v4.x),
                                          __float_as_uint(v4.y), 0x7632);
        const uint32_t hi23 = __byte_perm(__float_as_uint(v4.z),
                                          __float_as_uint(v4.w), 0x7632);
        const float l0 = v4.x - trunc_bf16(v4.x);
        const float l1 = v4.y - trunc_bf16(v4.y);
        const float l2 = v4.z - trunc_bf16(v4.z);
        const float l3 = v4.w - trunc_bf16(v4.w);
        const __nv_bfloat162 lp01 = __floats2bfloat162_rn(l0, l1);
        const __nv_bfloat162 lp23 = __floats2bfloat162_rn(l2, l3);
        const int qb = (q < 2) ? (q * 64 + sub * 8)
                               : (HALF_OFF + (q - 2) * 64 + sub * 8);
        *(uint2*)(rhi + qb) = make_uint2(hi01, hi23);
        *(uint2*)(rlo + qb) =
            make_uint2(*(const uint32_t*)&lp01, *(const uint32_t*)&lp23);
      }
    }
  }
  __syncthreads();

  if (!active) return;

  // ldmatrix addressing
  const uint32_t lrow = (lane < 16) ? lane : (lane - 16);
  const uint32_t lcol = (lane < 16) ? 0u : 16u;
  const uint32_t ahi_ld = sbase + PP_AHI + (wid * 16 + lrow) * AROW + lcol;
  const uint32_t alo_ld = sbase + PP_ALO + (wid * 16 + lrow) * AROW + lcol;

  float acc[16][4];
#pragma unroll
  for (int n = 0; n < 16; n++)
#pragma unroll
    for (int q = 0; q < 4; q++) acc[n][q] = 0.f;

#pragma unroll
  for (int ks = 0; ks < 8; ks++) {
    const uint32_t kb = ks * 32 + ((ks >= 4) ? 16u : 0u);
    uint32_t ah0, ah1, ah2, ah3, al0, al1, al2, al3;
    LDSM4(ah0, ah1, ah2, ah3, ahi_ld + kb);
    LDSM4(al0, al1, al2, al3, alo_ld + kb);
#pragma unroll
    for (int np = 0; np < 8; np++) {
      const uint4 vh = Bhi4[(ks * 8 + np) * 32 + lane];
      const uint4 vl = Blo4[(ks * 8 + np) * 32 + lane];
      MMA16816(acc[2 * np], ah0, ah1, ah2, ah3, vh.x, vh.y);
      MMA16816(acc[2 * np], ah0, ah1, ah2, ah3, vl.x, vl.y);
      MMA16816(acc[2 * np], al0, al1, al2, al3, vh.x, vh.y);
      MMA16816(acc[2 * np + 1], ah0, ah1, ah2, ah3, vh.z, vh.w);
      MMA16816(acc[2 * np + 1], ah0, ah1, ah2, ah3, vl.z, vl.w);
      MMA16816(acc[2 * np + 1], al0, al1, al2, al3, vh.z, vh.w);
    }
  }

  // store D -> g_Ph[p] as fp16 pairs
  __half* Pp = g_Ph + (size_t)p * NCAP * 128;
  const int r0 = n0 + (lane >> 2);
  const int r1 = r0 + 8;
#pragma unroll
  for (int nf = 0; nf < 16; nf++) {
    const int c0 = nf * 8 + (lane & 3) * 2;
    if (r0 < nodes)
      *(__half2*)(Pp + (size_t)r0 * 128 + c0) =
          __floats2half2_rn(acc[nf][0], acc[nf][1]);
    if (r1 < nodes)
      *(__half2*)(Pp + (size_t)r1 * 128 + c0) =
          __floats2half2_rn(acc[nf][2], acc[nf][3]);
  }
}

// ---------------------------------------------------------------------------
// Kernel B: per-group context term (+ b1 folded in), fp16 in/out
// ---------------------------------------------------------------------------
__global__ __launch_bounds__(128) void group_ctx(
    const int* __restrict__ indices, const float* __restrict__ b1, int G) {
  const int g = blockIdx.x;
  if (g >= G) return;
  const int t = threadIdx.x;
  const int* ip = indices + (size_t)g * 25 * 23 + 3;
  const __half* Pc = g_Ph + (size_t)2 * NCAP * 128;

  float s = 0.f;
  int cnt = 0;
#pragma unroll
  for (int kk = 0; kk < 20; kk++) {
    const int id = ip[kk];
    s += __half2float(Pc[(size_t)id * 128 + t]);
    cnt += (id > 0) ? 1 : 0;
  }
  const float norm = (float)(cnt > 0 ? cnt : 1);
  g_Gch[(size_t)g * 128 + t] = __float2half(s / norm + b1[t]);
}

// ---------------------------------------------------------------------------
// Kernel C: warp-independent SINGLE-PASS fp16 HMMA MLP. Each warp owns a
// 16-row tile. fp16 gathers; h1 and W2 in fp16 (inputs only carry fp16
// precision anyway); fp32 accumulate. 1/3 the MMAs, half the smem traffic.
// ---------------------------------------------------------------------------
#define M_A_OFF 0                          // 8 warps * 16 rows * AROW = 34816
#define M_BF_OFF (8 * 16 * AROW)           // 34816
#define M_BFRAG_U4 1024
#define M_MISC_OFF (M_BF_OFF + M_BFRAG_U4 * 16)   // 51200
#define M_SMEM (M_MISC_OFF + 768)

__global__ void __launch_bounds__(256, 2) mlp_main_mma(
    const int* __restrict__ indices,
    const float* __restrict__ b2, const float* __restrict__ W3,
    const float* __restrict__ b3,
    float* __restrict__ out, int N) {
  extern __shared__ char smem[];
  const uint32_t sbase = smem_u32(smem);

  const int tid = threadIdx.x;
  const int wid = tid >> 5;
  const int lane = tid & 31;

  uint4* Bf4 = (uint4*)(smem + M_BF_OFF);    // [ks][np][lane], fp16
  float* b2s = (float*)(smem + M_MISC_OFF);
  float* w3s = b2s + 64;

  // ---- coalesced W2 fp16 fragment copy (prebuilt, table 3) ----
  {
    const uint4* sh = g_Wf_hi[3];
    for (int i = tid; i < M_BFRAG_U4; i += 256) Bf4[i] = sh[i];
  }
  if (tid < 64) { b2s[tid] = b2[tid]; w3s[tid] = W3[tid]; }
  const float b3v = b3[0];
  __syncthreads();

  const char* PaB = (const char*)g_Ph;
  const char* PbB = (const char*)(g_Ph + (size_t)NCAP * 128);
  const char* GcB = (const char*)g_Gch;

  const int sub = lane & 7;          // 16B sub-block (8 fp16 ch) within a row
  const int rgl = lane >> 3;         // row within group of 4
  char* tile_a = smem + M_A_OFF + (size_t)(wid * 16) * AROW;

  const uint32_t lrow = (lane < 16) ? lane : (lane - 16);
  const uint32_t lcol = (lane < 16) ? 0u : 16u;
  const uint32_t a_ld = sbase + M_A_OFF + (wid * 16 + lrow) * AROW + lcol;

  const int NTW = (N + 15) >> 4;
  const int wstride = gridDim.x * 8;

  for (int wt = blockIdx.x * 8 + wid; wt < NTW; wt += wstride) {
    const int rbase = wt << 4;

    // ---- Phase A: fp16 gather + relu -> fp16 A tile ----
#pragma unroll
    for (int rg = 0; rg < 4; rg++) {
      const int r = rg * 4 + rgl;
      const int gr = min(rbase + r, N - 1);
      const int i0 = indices[(size_t)gr * 23 + 0];
      const int i1 = indices[(size_t)gr * 23 + 1];
      const int g = gr / 25;
      const char* pa = PaB + (size_t)i0 * 256;
      const char* pb = PbB + (size_t)i1 * 256;
      const char* gc = GcB + (size_t)g * 256;
      char* ra = tile_a + (size_t)r * AROW;
#pragma unroll
      for (int q = 0; q < 2; q++) {
        const int off = q * 128 + sub * 16;   // 8 fp16 channels
        const uint4 ua = *(const uint4*)(pa + off);
        const uint4 ub = *(const uint4*)(pb + off);
        const uint4 ug = *(const uint4*)(gc + off);
        const __half2* ha = (const __half2*)&ua;
        const __half2* hb = (const __half2*)&ub;
        const __half2* hg = (const __half2*)&ug;
        uint32_t hp[4];
#pragma unroll
        for (int j = 0; j < 4; j++) {
          const float2 fa = __half22float2(ha[j]);
          const float2 fb = __half22float2(hb[j]);
          const float2 fg = __half22float2(hg[j]);
          hp[j] = hpack(fmaxf(fa.x + fb.x + fg.x, 0.f),
                        fmaxf(fa.y + fb.y + fg.y, 0.f));
        }
        const int qb = (q == 0) ? (sub * 16) : (HALF_OFF + sub * 16);
        *(uint4*)(ra + qb) = make_uint4(hp[0], hp[1], hp[2], hp[3]);
      }
    }
    __syncwarp();

    // ---- Phase B: single-pass fp16 HMMA ----
    float acc[8][4];
#pragma unroll
    for (int n = 0; n < 8; n++)
#pragma unroll
      for (int q = 0; q < 4; q++) acc[n][q] = 0.f;

#pragma unroll
    for (int ks = 0; ks < 8; ks++) {
      const uint32_t kb = ks * 32 + ((ks >= 4) ? 16u : 0u);
      uint32_t a0, a1, a2, a3;
      LDSM4(a0, a1, a2, a3, a_ld + kb);
#pragma unroll
      for (int np = 0; np < 4; np++) {
        const uint4 vb = Bf4[(ks * 4 + np) * 32 + lane];
        MMA16816H(acc[2 * np], a0, a1, a2, a3, vb.x, vb.y);
        MMA16816H(acc[2 * np + 1], a0, a1, a2, a3, vb.z, vb.w);
      }
    }

    // ---- Epilogue ----
    float s0 = 0.f, s1 = 0.f;
#pragma unroll
    for (int n = 0; n < 8; n++) {
      const int c0 = n * 8 + (lane & 3) * 2;
      const float2 b2p = *(const float2*)(b2s + c0);
      const float2 w3p = *(const float2*)(w3s + c0);
      s0 = fmaf(fmaxf(acc[n][0] + b2p.x, 0.f), w3p.x, s0);
      s0 = fmaf(fmaxf(acc[n][1] + b2p.y, 0.f), w3p.y, s0);
      s1 = fmaf(fmaxf(acc[n][2] + b2p.x, 0.f), w3p.x, s1);
      s1 = fmaf(fmaxf(acc[n][3] + b2p.y, 0.f), w3p.y, s1);
    }
    s0 += __shfl_xor_sync(0xffffffffu, s0, 1);
    s0 += __shfl_xor_sync(0xffffffffu, s0, 2);
    s1 += __shfl_xor_sync(0xffffffffu, s1, 1);
    s1 += __shfl_xor_sync(0xffffffffu, s1, 2);
    if ((lane & 3) == 0) {
      const int r0 = rbase + (lane >> 2);
      if (r0 < N) out[r0] = s0 + b3v;
      const int r1 = r0 + 8;
      if (r1 < N) out[r1] = s1 + b3v;
    }
    __syncwarp();   // protect smem tile reuse next iteration
  }
}

// ---------------------------------------------------------------------------
extern "C" void kernel_launch(void* const* d_in, const int* in_sizes, int n_in,
                              void* d_out, int out_size) {
  const int* indices = (const int*)d_in[0];
  // d_in[1] = nr (fixed 24)
  const float* x  = (const float*)d_in[2];
  const float* W1 = (const float*)d_in[3];
  const float* b1 = (const float*)d_in[4];
  const float* W2 = (const float*)d_in[5];
  const float* b2 = (const float*)d_in[6];
  const float* W3 = (const float*)d_in[7];
  const float* b3 = (const float*)d_in[8];
  float* out = (float*)d_out;

  const int N = in_sizes[0] / 23;          // 500000
  const int nodes = in_sizes[2] / 128;     // 10000
  const int G = (N - 2) / 25 + 1;          // 20000 groups
  const int ntiles = (nodes + 15) / 16;    // 625

  cudaFuncSetAttribute(precompute_P_tc,
                       cudaFuncAttributeMaxDynamicSharedMemorySize, PP_SMEM);
  cudaFuncSetAttribute(mlp_main_mma,
                       cudaFuncAttributeMaxDynamicSharedMemorySize, M_SMEM);

  dim3 gridW(8, 4);
  build_wfrags<<<gridW, 256>>>(W1, W2);
  dim3 gridP((ntiles + 3) / 4, 3);
  precompute_P_tc<<<gridP, 128, PP_SMEM>>>(x, nodes);
  group_ctx<<<G, 128>>>(indices, b1, G);
  mlp_main_mma<<<296, 256, M_SMEM>>>(indices, b2, W3, b3, out, N);
}

// round 16
// speedup vs baseline: 1.5602x; 1.0230x over previous
#include <cuda_runtime.h>
#include <cuda_bf16.h>
#include <cuda_fp16.h>
#include <cstdint>

#define NCAP 10240            // node capacity for P tables
#define GCAP 20032            // group capacity

// Scratch (device globals: no allocations allowed). P/Gc in fp16.
__device__ __half g_Ph[3 * NCAP * 128];  // Pa | Pb | Pc
__device__ __half g_Gch[GCAP * 128];     // per-group ctx term (+ b1 folded)

// Prebuilt weight fragments:
//  tables 0..2 = W1 parts, bf16 hi/lo (2048 u4 each) for 3-pass precompute
//  table  3    = W2, fp16 single-pass (1024 u4, hi only)
__device__ uint4 g_Wf_hi[4][2048];
__device__ uint4 g_Wf_lo[4][2048];

// ---------------------------------------------------------------------------
// helpers
// ---------------------------------------------------------------------------
__device__ __forceinline__ uint32_t smem_u32(const void* p) {
  uint32_t a;
  asm("{ .reg .u64 t; cvta.to.shared.u64 t, %1; cvt.u32.u64 %0, t; }"
      : "=r"(a) : "l"(p));
  return a;
}

__device__ __forceinline__ uint32_t bpack(__nv_bfloat16 a, __nv_bfloat16 b) {
  __nv_bfloat162 t(a, b);          // .x = a (low half)
  return *reinterpret_cast<uint32_t*>(&t);
}

__device__ __forceinline__ uint32_t hpack(float a, float b) {
  __half2 t = __floats2half2_rn(a, b);
  return *reinterpret_cast<uint32_t*>(&t);
}

#define LDSM4(r0, r1, r2, r3, addr)                                          \
  asm volatile(                                                              \
      "ldmatrix.sync.aligned.m8n8.x4.shared.b16 {%0,%1,%2,%3}, [%4];"        \
      : "=r"(r0), "=r"(r1), "=r"(r2), "=r"(r3) : "r"(addr))

#define MMA16816(d, a0, a1, a2, a3, b0, b1)                                  \
  asm volatile(                                                              \
      "mma.sync.aligned.m16n8k16.row.col.f32.bf16.bf16.f32 "                 \
      "{%0,%1,%2,%3}, {%4,%5,%6,%7}, {%8,%9}, {%0,%1,%2,%3};"                \
      : "+f"((d)[0]), "+f"((d)[1]), "+f"((d)[2]), "+f"((d)[3])               \
      : "r"(a0), "r"(a1), "r"(a2), "r"(a3), "r"(b0), "r"(b1))

#define MMA16816H(d, a0, a1, a2, a3, b0, b1)                                 \
  asm volatile(                                                              \
      "mma.sync.aligned.m16n8k16.row.col.f32.f16.f16.f32 "                   \
      "{%0,%1,%2,%3}, {%4,%5,%6,%7}, {%8,%9}, {%0,%1,%2,%3};"                \
      : "+f"((d)[0]), "+f"((d)[1]), "+f"((d)[2]), "+f"((d)[3])               \
      : "r"(a0), "r"(a1), "r"(a2), "r"(a3), "r"(b0), "r"(b1))

// truncate fp32 to bf16 (toward zero); exact residual in fp32
__device__ __forceinline__ float trunc_bf16(float v) {
  return __uint_as_float(__float_as_uint(v) & 0xffff0000u);
}

// Common A-tile geometry (shared by both MMA kernels)
#define AROW 272                       // bytes per 128-ch row (16-aligned halves)
#define HALF_OFF 144                   // byte offset of channels 64..127

// build one hi/lo bf16 B-fragment uint4 pair from two weight rows
__device__ __forceinline__ void build_bfrag(const float* w_base, int row_stride,
                                            int ng0, int ng1, int k0,
                                            uint4* hi, uint4* lo) {
  uint32_t hx[2], hy[2], lx[2], ly[2];
  const int ngs[2] = {ng0, ng1};
#pragma unroll
  for (int t = 0; t < 2; t++) {
    const float* wr = w_base + (size_t)ngs[t] * row_stride + k0;
    const float w00 = wr[0], w01 = wr[1], w10 = wr[8], w11 = wr[9];
    __nv_bfloat16 h00 = __float2bfloat16(w00);
    __nv_bfloat16 h01 = __float2bfloat16(w01);
    __nv_bfloat16 h10 = __float2bfloat16(w10);
    __nv_bfloat16 h11 = __float2bfloat16(w11);
    __nv_bfloat16 l00 = __float2bfloat16(w00 - __bfloat162float(h00));
    __nv_bfloat16 l01 = __float2bfloat16(w01 - __bfloat162float(h01));
    __nv_bfloat16 l10 = __float2bfloat16(w10 - __bfloat162float(h10));
    __nv_bfloat16 l11 = __float2bfloat16(w11 - __bfloat162float(h11));
    hx[t] = bpack(h00, h01); hy[t] = bpack(h10, h11);
    lx[t] = bpack(l00, l01); ly[t] = bpack(l10, l11);
  }
  *hi = make_uint4(hx[0], hy[0], hx[1], hy[1]);
  *lo = make_uint4(lx[0], ly[0], lx[1], ly[1]);
}

// ---------------------------------------------------------------------------
// Kernel 0: build all weight fragments ONCE into device globals.
// ---------------------------------------------------------------------------
__global__ __launch_bounds__(256) void build_wfrags(
    const float* __restrict__ W1, const float* __restrict__ W2) {
  const int tab = blockIdx.y;
  const int i = blockIdx.x * 256 + threadIdx.x;
  const int count = (tab == 3) ? 1024 : 2048;
  if (i >= count) return;

  const int ln = i & 31;
  const int npw = (tab == 3) ? ((i >> 5) & 3) : ((i >> 5) & 7);
  const int ks = (tab == 3) ? (i >> 7) : (i >> 8);
  const int k0 = ks * 16 + (ln & 3) * 2;
  const int ng0 = (2 * npw) * 8 + (ln >> 2);
  const int ng1 = (2 * npw + 1) * 8 + (ln >> 2);

  if (tab == 3) {
    // W2 as fp16 single-pass fragments
    uint32_t hx[2], hy[2];
    const int ngs[2] = {ng0, ng1};
#pragma unroll
    for (int t = 0; t < 2; t++) {
      const float* wr = W2 + (size_t)ngs[t] * 128 + k0;
      hx[t] = hpack(wr[0], wr[1]);
      hy[t] = hpack(wr[8], wr[9]);
    }
    g_Wf_hi[3][i] = make_uint4(hx[0], hy[0], hx[1], hy[1]);
  } else {
    uint4 hi, lo;
    build_bfrag(W1 + tab * 128, 384, ng0, ng1, k0, &hi, &lo);
    g_Wf_hi[tab][i] = hi;
    g_Wf_lo[tab][i] = lo;
  }
}

// ---------------------------------------------------------------------------
// Kernel A (tensor, PERSISTENT): P[p][n][j] = sum_k x[n][k]*W1[j][p*128+k]
// grid (98, 3): blockIdx.y = part. Each block copies its part's fragments
// ONCE, then each warp loops over ~6 tiles (A-split -> 3-pass MMA -> fp16
// store) with only __syncwarp between iterations. No wave tail.
// ---------------------------------------------------------------------------
#define PP_AHI 0
#define PP_ALO (4 * 16 * AROW)             // 17408
#define PP_BHI (2 * 4 * 16 * AROW)         // 34816
#define PP_BLO (PP_BHI + 32768)            // 67584
#define PP_SMEM (PP_BLO + 32768)           // 100352

__global__ void __launch_bounds__(128, 2) precompute_P_tc(
    const float* __restrict__ x, int nodes) {
  extern __shared__ char smem[];
  const uint32_t sbase = smem_u32(smem);
  const int tid = threadIdx.x;
  const int wid = tid >> 5;
  const int lane = tid & 31;
  const int p = blockIdx.y;

  uint4* Bhi4 = (uint4*)(smem + PP_BHI);   // [ks][np][lane], np=0..7 (16 nf)
  uint4* Blo4 = (uint4*)(smem + PP_BLO);

  // ---- coalesced fragment copy from global (prebuilt), ONCE ----
  {
    const uint4* sh = g_Wf_hi[p];
    const uint4* sl = g_Wf_lo[p];
    for (int i = tid; i < 2048; i += 128) {
      Bhi4[i] = sh[i];
      Blo4[i] = sl[i];
    }
  }
  __syncthreads();

  const int sub = lane & 7;
  const int rgl = lane >> 3;
  char* tile_hi = smem + PP_AHI + (size_t)wid * 16 * AROW;
  char* tile_lo = smem + PP_ALO + (size_t)wid * 16 * AROW;

  const uint32_t lrow = (lane < 16) ? lane : (lane - 16);
  const uint32_t lcol = (lane < 16) ? 0u : 16u;
  const uint32_t ahi_ld = sbase + PP_AHI + (wid * 16 + lrow) * AROW + lcol;
  const uint32_t alo_ld = sbase + PP_ALO + (wid * 16 + lrow) * AROW + lcol;

  __half* Pp = g_Ph + (size_t)p * NCAP * 128;
  const int ntiles = (nodes + 15) >> 4;
  const int wstride = gridDim.x * 4;

  for (int wt = blockIdx.x * 4 + wid; wt < ntiles; wt += wstride) {
    const int n0 = wt << 4;

    // ---- A split: 16 x-rows -> trunc hi/lo bf16 in AROW layout ----
#pragma unroll
    for (int rg = 0; rg < 4; rg++) {
      const int r = rg * 4 + rgl;
      const int gr = min(n0 + r, nodes - 1);
      const float* xr = x + (size_t)gr * 128;
      char* rhi = tile_hi + (size_t)r * AROW;
      char* rlo = tile_lo + (size_t)r * AROW;
#pragma unroll
      for (int q = 0; q < 4; q++) {
        const int c = q * 32 + sub * 4;
        const float4 v4 = *(const float4*)(xr + c);
        const uint32_t hi01 = __byte_perm(__float_as_uint(v4.x),
                                          __float_as_uint(v4.y), 0x7632);
        const uint32_t hi23 = __byte_perm(__float_as_uint(v4.z),
                                          __float_as_uint(v4.w), 0x7632);
        const float l0 = v4.x - trunc_bf16(v4.x);
        const float l1 = v4.y - trunc_bf16(v4.y);
        const float l2 = v4.z - trunc_bf16(v4.z);
        const float l3 = v4.w - trunc_bf16(v4.w);
        const __nv_bfloat162 lp01 = __floats2bfloat162_rn(l0, l1);
        const __nv_bfloat162 lp23 = __floats2bfloat162_rn(l2, l3);
        const int qb = (q < 2) ? (q * 64 + sub * 8)
                               : (HALF_OFF + (q - 2) * 64 + sub * 8);
        *(uint2*)(rhi + qb) = make_uint2(hi01, hi23);
        *(uint2*)(rlo + qb) =
            make_uint2(*(const uint32_t*)&lp01, *(const uint32_t*)&lp23);
      }
    }
    __syncwarp();

    float acc[16][4];
#pragma unroll
    for (int n = 0; n < 16; n++)
#pragma unroll
      for (int q = 0; q < 4; q++) acc[n][q] = 0.f;

#pragma unroll
    for (int ks = 0; ks < 8; ks++) {
      const uint32_t kb = ks * 32 + ((ks >= 4) ? 16u : 0u);
      uint32_t ah0, ah1, ah2, ah3, al0, al1, al2, al3;
      LDSM4(ah0, ah1, ah2, ah3, ahi_ld + kb);
      LDSM4(al0, al1, al2, al3, alo_ld + kb);
#pragma unroll
      for (int np = 0; np < 8; np++) {
        const uint4 vh = Bhi4[(ks * 8 + np) * 32 + lane];
        const uint4 vl = Blo4[(ks * 8 + np) * 32 + lane];
        MMA16816(acc[2 * np], ah0, ah1, ah2, ah3, vh.x, vh.y);
        MMA16816(acc[2 * np], ah0, ah1, ah2, ah3, vl.x, vl.y);
        MMA16816(acc[2 * np], al0, al1, al2, al3, vh.x, vh.y);
        MMA16816(acc[2 * np + 1], ah0, ah1, ah2, ah3, vh.z, vh.w);
        MMA16816(acc[2 * np + 1], ah0, ah1, ah2, ah3, vl.z, vl.w);
        MMA16816(acc[2 * np + 1], al0, al1, al2, al3, vh.z, vh.w);
      }
    }

    // store D -> g_Ph[p] as fp16 pairs
    const int r0 = n0 + (lane >> 2);
    const int r1 = r0 + 8;
#pragma unroll
    for (int nf = 0; nf < 16; nf++) {
      const int c0 = nf * 8 + (lane & 3) * 2;
      if (r0 < nodes)
        *(__half2*)(Pp + (size_t)r0 * 128 + c0) =
            __floats2half2_rn(acc[nf][0], acc[nf][1]);
      if (r1 < nodes)
        *(__half2*)(Pp + (size_t)r1 * 128 + c0) =
            __floats2half2_rn(acc[nf][2], acc[nf][3]);
    }
    __syncwarp();   // protect this warp's A region before next iteration
  }
}

// ---------------------------------------------------------------------------
// Kernel B: per-group context term (+ b1 folded in), fp16 in/out
// ---------------------------------------------------------------------------
__global__ __launch_bounds__(128) void group_ctx(
    const int* __restrict__ indices, const float* __restrict__ b1, int G) {
  const int g = blockIdx.x;
  if (g >= G) return;
  const int t = threadIdx.x;
  const int* ip = indices + (size_t)g * 25 * 23 + 3;
  const __half* Pc = g_Ph + (size_t)2 * NCAP * 128;

  float s = 0.f;
  int cnt = 0;
#pragma unroll
  for (int kk = 0; kk < 20; kk++) {
    const int id = ip[kk];
    s += __half2float(Pc[(size_t)id * 128 + t]);
    cnt += (id > 0) ? 1 : 0;
  }
  const float norm = (float)(cnt > 0 ? cnt : 1);
  g_Gch[(size_t)g * 128 + t] = __float2half(s / norm + b1[t]);
}

// ---------------------------------------------------------------------------
// Kernel C: warp-independent SINGLE-PASS fp16 HMMA MLP (unchanged from R15).
// ---------------------------------------------------------------------------
#define M_A_OFF 0                          // 8 warps * 16 rows * AROW = 34816
#define M_BF_OFF (8 * 16 * AROW)           // 34816
#define M_BFRAG_U4 1024
#define M_MISC_OFF (M_BF_OFF + M_BFRAG_U4 * 16)   // 51200
#define M_SMEM (M_MISC_OFF + 768)

__global__ void __launch_bounds__(256, 2) mlp_main_mma(
    const int* __restrict__ indices,
    const float* __restrict__ b2, const float* __restrict__ W3,
    const float* __restrict__ b3,
    float* __restrict__ out, int N) {
  extern __shared__ char smem[];
  const uint32_t sbase = smem_u32(smem);

  const int tid = threadIdx.x;
  const int wid = tid >> 5;
  const int lane = tid & 31;

  uint4* Bf4 = (uint4*)(smem + M_BF_OFF);    // [ks][np][lane], fp16
  float* b2s = (float*)(smem + M_MISC_OFF);
  float* w3s = b2s + 64;

  // ---- coalesced W2 fp16 fragment copy (prebuilt, table 3) ----
  {
    const uint4* sh = g_Wf_hi[3];
    for (int i = tid; i < M_BFRAG_U4; i += 256) Bf4[i] = sh[i];
  }
  if (tid < 64) { b2s[tid] = b2[tid]; w3s[tid] = W3[tid]; }
  const float b3v = b3[0];
  __syncthreads();

  const char* PaB = (const char*)g_Ph;
  const char* PbB = (const char*)(g_Ph + (size_t)NCAP * 128);
  const char* GcB = (const char*)g_Gch;

  const int sub = lane & 7;          // 16B sub-block (8 fp16 ch) within a row
  const int rgl = lane >> 3;         // row within group of 4
  char* tile_a = smem + M_A_OFF + (size_t)(wid * 16) * AROW;

  const uint32_t lrow = (lane < 16) ? lane : (lane - 16);
  const uint32_t lcol = (lane < 16) ? 0u : 16u;
  const uint32_t a_ld = sbase + M_A_OFF + (wid * 16 + lrow) * AROW + lcol;

  const int NTW = (N + 15) >> 4;
  const int wstride = gridDim.x * 8;

  for (int wt = blockIdx.x * 8 + wid; wt < NTW; wt += wstride) {
    const int rbase = wt << 4;

    // ---- Phase A: fp16 gather + relu -> fp16 A tile ----
#pragma unroll
    for (int rg = 0; rg < 4; rg++) {
      const int r = rg * 4 + rgl;
      const int gr = min(rbase + r, N - 1);
      const int i0 = indices[(size_t)gr * 23 + 0];
      const int i1 = indices[(size_t)gr * 23 + 1];
      const int g = gr / 25;
      const char* pa = PaB + (size_t)i0 * 256;
      const char* pb = PbB + (size_t)i1 * 256;
      const char* gc = GcB + (size_t)g * 256;
      char* ra = tile_a + (size_t)r * AROW;
#pragma unroll
      for (int q = 0; q < 2; q++) {
        const int off = q * 128 + sub * 16;   // 8 fp16 channels
        const uint4 ua = *(const uint4*)(pa + off);
        const uint4 ub = *(const uint4*)(pb + off);
        const uint4 ug = *(const uint4*)(gc + off);
        const __half2* ha = (const __half2*)&ua;
        const __half2* hb = (const __half2*)&ub;
        const __half2* hg = (const __half2*)&ug;
        uint32_t hp[4];
#pragma unroll
        for (int j = 0; j < 4; j++) {
          const float2 fa = __half22float2(ha[j]);
          const float2 fb = __half22float2(hb[j]);
          const float2 fg = __half22float2(hg[j]);
          hp[j] = hpack(fmaxf(fa.x + fb.x + fg.x, 0.f),
                        fmaxf(fa.y + fb.y + fg.y, 0.f));
        }
        const int qb = (q == 0) ? (sub * 16) : (HALF_OFF + sub * 16);
        *(uint4*)(ra + qb) = make_uint4(hp[0], hp[1], hp[2], hp[3]);
      }
    }
    __syncwarp();

    // ---- Phase B: single-pass fp16 HMMA ----
    float acc[8][4];
#pragma unroll
    for (int n = 0; n < 8; n++)
#pragma unroll
      for (int q = 0; q < 4; q++) acc[n][q] = 0.f;

#pragma unroll
    for (int ks = 0; ks < 8; ks++) {
      const uint32_t kb = ks * 32 + ((ks >= 4) ? 16u : 0u);
      uint32_t a0, a1, a2, a3;
      LDSM4(a0, a1, a2, a3, a_ld + kb);
#pragma unroll
      for (int np = 0; np < 4; np++) {
        const uint4 vb = Bf4[(ks * 4 + np) * 32 + lane];
        MMA16816H(acc[2 * np], a0, a1, a2, a3, vb.x, vb.y);
        MMA16816H(acc[2 * np + 1], a0, a1, a2, a3, vb.z, vb.w);
      }
    }

    // ---- Epilogue ----
    float s0 = 0.f, s1 = 0.f;
#pragma unroll
    for (int n = 0; n < 8; n++) {
      const int c0 = n * 8 + (lane & 3) * 2;
      const float2 b2p = *(const float2*)(b2s + c0);
      const float2 w3p = *(const float2*)(w3s + c0);
      s0 = fmaf(fmaxf(acc[n][0] + b2p.x, 0.f), w3p.x, s0);
      s0 = fmaf(fmaxf(acc[n][1] + b2p.y, 0.f), w3p.y, s0);
      s1 = fmaf(fmaxf(acc[n][2] + b2p.x, 0.f), w3p.x, s1);
      s1 = fmaf(fmaxf(acc[n][3] + b2p.y, 0.f), w3p.y, s1);
    }
    s0 += __shfl_xor_sync(0xffffffffu, s0, 1);
    s0 += __shfl_xor_sync(0xffffffffu, s0, 2);
    s1 += __shfl_xor_sync(0xffffffffu, s1, 1);
    s1 += __shfl_xor_sync(0xffffffffu, s1, 2);
    if ((lane & 3) == 0) {
      const int r0 = rbase + (lane >> 2);
      if (r0 < N) out[r0] = s0 + b3v;
      const int r1 = r0 + 8;
      if (r1 < N) out[r1] = s1 + b3v;
    }
    __syncwarp();   // protect smem tile reuse next iteration
  }
}

// ---------------------------------------------------------------------------
extern "C" void kernel_launch(void* const* d_in, const int* in_sizes, int n_in,
                              void* d_out, int out_size) {
  const int* indices = (const int*)d_in[0];
  // d_in[1] = nr (fixed 24)
  const float* x  = (const float*)d_in[2];
  const float* W1 = (const float*)d_in[3];
  const float* b1 = (const float*)d_in[4];
  const float* W2 = (const float*)d_in[5];
  const float* b2 = (const float*)d_in[6];
  const float* W3 = (const float*)d_in[7];
  const float* b3 = (const float*)d_in[8];
  float* out = (float*)d_out;

  const int N = in_sizes[0] / 23;          // 500000
  const int nodes = in_sizes[2] / 128;     // 10000
  const int G = (N - 2) / 25 + 1;          // 20000 groups

  cudaFuncSetAttribute(precompute_P_tc,
                       cudaFuncAttributeMaxDynamicSharedMemorySize, PP_SMEM);
  cudaFuncSetAttribute(mlp_main_mma,
                       cudaFuncAttributeMaxDynamicSharedMemorySize, M_SMEM);

  dim3 gridW(8, 4);
  build_wfrags<<<gridW, 256>>>(W1, W2);
  dim3 gridP(98, 3);                       // persistent: ~2 blocks/SM total
  precompute_P_tc<<<gridP, 128, PP_SMEM>>>(x, nodes);
  group_ctx<<<G, 128>>>(indices, b1, G);
  mlp_main_mma<<<296, 256, M_SMEM>>>(indices, b2, W3, b3, out, N);
}

// round 17
// speedup vs baseline: 1.6015x; 1.0265x over previous
#include <cuda_runtime.h>
#include <cuda_bf16.h>
#include <cuda_fp16.h>
#include <cstdint>

#define NCAP 10240            // node capacity for P tables
#define GCAP 20032            // group capacity

// Scratch (device globals: no allocations allowed). P/Gc in fp16.
__device__ __half g_Ph[3 * NCAP * 128];  // Pa | Pb | Pc
__device__ __half g_Gch[GCAP * 128];     // per-group ctx term (+ b1 folded)

// Prebuilt weight fragments:
//  tables 0..2 = W1 parts, bf16 hi/lo (2048 u4 each) for 3-pass precompute
//  table  3    = W2, fp16 single-pass (1024 u4, hi only)
__device__ uint4 g_Wf_hi[4][2048];
__device__ uint4 g_Wf_lo[4][2048];

// ---------------------------------------------------------------------------
// helpers
// ---------------------------------------------------------------------------
__device__ __forceinline__ uint32_t smem_u32(const void* p) {
  uint32_t a;
  asm("{ .reg .u64 t; cvta.to.shared.u64 t, %1; cvt.u32.u64 %0, t; }"
      : "=r"(a) : "l"(p));
  return a;
}

__device__ __forceinline__ uint32_t bpack(__nv_bfloat16 a, __nv_bfloat16 b) {
  __nv_bfloat162 t(a, b);          // .x = a (low half)
  return *reinterpret_cast<uint32_t*>(&t);
}

__device__ __forceinline__ uint32_t hpack(float a, float b) {
  __half2 t = __floats2half2_rn(a, b);
  return *reinterpret_cast<uint32_t*>(&t);
}

#define LDSM4(r0, r1, r2, r3, addr)                                          \
  asm volatile(                                                              \
      "ldmatrix.sync.aligned.m8n8.x4.shared.b16 {%0,%1,%2,%3}, [%4];"        \
      : "=r"(r0), "=r"(r1), "=r"(r2), "=r"(r3) : "r"(addr))

#define MMA16816(d, a0, a1, a2, a3, b0, b1)                                  \
  asm volatile(                                                              \
      "mma.sync.aligned.m16n8k16.row.col.f32.bf16.bf16.f32 "                 \
      "{%0,%1,%2,%3}, {%4,%5,%6,%7}, {%8,%9}, {%0,%1,%2,%3};"                \
      : "+f"((d)[0]), "+f"((d)[1]), "+f"((d)[2]), "+f"((d)[3])               \
      : "r"(a0), "r"(a1), "r"(a2), "r"(a3), "r"(b0), "r"(b1))

#define MMA16816H(d, a0, a1, a2, a3, b0, b1)                                 \
  asm volatile(                                                              \
      "mma.sync.aligned.m16n8k16.row.col.f32.f16.f16.f32 "                   \
      "{%0,%1,%2,%3}, {%4,%5,%6,%7}, {%8,%9}, {%0,%1,%2,%3};"                \
      : "+f"((d)[0]), "+f"((d)[1]), "+f"((d)[2]), "+f"((d)[3])               \
      : "r"(a0), "r"(a1), "r"(a2), "r"(a3), "r"(b0), "r"(b1))

// truncate fp32 to bf16 (toward zero); exact residual in fp32
__device__ __forceinline__ float trunc_bf16(float v) {
  return __uint_as_float(__float_as_uint(v) & 0xffff0000u);
}

// Common A-tile geometry (shared by both MMA kernels)
#define AROW 272                       // bytes per 128-ch row (16-aligned halves)
#define HALF_OFF 144                   // byte offset of channels 64..127

// build one hi/lo bf16 B-fragment uint4 pair from two weight rows
__device__ __forceinline__ void build_bfrag(const float* w_base, int row_stride,
                                            int ng0, int ng1, int k0,
                                            uint4* hi, uint4* lo) {
  uint32_t hx[2], hy[2], lx[2], ly[2];
  const int ngs[2] = {ng0, ng1};
#pragma unroll
  for (int t = 0; t < 2; t++) {
    const float* wr = w_base + (size_t)ngs[t] * row_stride + k0;
    const float w00 = wr[0], w01 = wr[1], w10 = wr[8], w11 = wr[9];
    __nv_bfloat16 h00 = __float2bfloat16(w00);
    __nv_bfloat16 h01 = __float2bfloat16(w01);
    __nv_bfloat16 h10 = __float2bfloat16(w10);
    __nv_bfloat16 h11 = __float2bfloat16(w11);
    __nv_bfloat16 l00 = __float2bfloat16(w00 - __bfloat162float(h00));
    __nv_bfloat16 l01 = __float2bfloat16(w01 - __bfloat162float(h01));
    __nv_bfloat16 l10 = __float2bfloat16(w10 - __bfloat162float(h10));
    __nv_bfloat16 l11 = __float2bfloat16(w11 - __bfloat162float(h11));
    hx[t] = bpack(h00, h01); hy[t] = bpack(h10, h11);
    lx[t] = bpack(l00, l01); ly[t] = bpack(l10, l11);
  }
  *hi = make_uint4(hx[0], hy[0], hx[1], hy[1]);
  *lo = make_uint4(lx[0], ly[0], lx[1], ly[1]);
}

// ---------------------------------------------------------------------------
// Kernel 0: build all weight fragments ONCE into device globals.
// ---------------------------------------------------------------------------
__global__ __launch_bounds__(256) void build_wfrags(
    const float* __restrict__ W1, const float* __restrict__ W2) {
  const int tab = blockIdx.y;
  const int i = blockIdx.x * 256 + threadIdx.x;
  const int count = (tab == 3) ? 1024 : 2048;
  if (i >= count) return;

  const int ln = i & 31;
  const int npw = (tab == 3) ? ((i >> 5) & 3) : ((i >> 5) & 7);
  const int ks = (tab == 3) ? (i >> 7) : (i >> 8);
  const int k0 = ks * 16 + (ln & 3) * 2;
  const int ng0 = (2 * npw) * 8 + (ln >> 2);
  const int ng1 = (2 * npw + 1) * 8 + (ln >> 2);

  if (tab == 3) {
    // W2 as fp16 single-pass fragments
    uint32_t hx[2], hy[2];
    const int ngs[2] = {ng0, ng1};
#pragma unroll
    for (int t = 0; t < 2; t++) {
      const float* wr = W2 + (size_t)ngs[t] * 128 + k0;
      hx[t] = hpack(wr[0], wr[1]);
      hy[t] = hpack(wr[8], wr[9]);
    }
    g_Wf_hi[3][i] = make_uint4(hx[0], hy[0], hx[1], hy[1]);
  } else {
    uint4 hi, lo;
    build_bfrag(W1 + tab * 128, 384, ng0, ng1, k0, &hi, &lo);
    g_Wf_hi[tab][i] = hi;
    g_Wf_lo[tab][i] = lo;
  }
}

// ---------------------------------------------------------------------------
// Kernel A (tensor, PERSISTENT): P[p][n][j] = sum_k x[n][k]*W1[j][p*128+k]
// grid (98, 3): blockIdx.y = part. Fragments copied once; warps loop tiles.
// ---------------------------------------------------------------------------
#define PP_AHI 0
#define PP_ALO (4 * 16 * AROW)             // 17408
#define PP_BHI (2 * 4 * 16 * AROW)         // 34816
#define PP_BLO (PP_BHI + 32768)            // 67584
#define PP_SMEM (PP_BLO + 32768)           // 100352

__global__ void __launch_bounds__(128, 2) precompute_P_tc(
    const float* __restrict__ x, int nodes) {
  extern __shared__ char smem[];
  const uint32_t sbase = smem_u32(smem);
  const int tid = threadIdx.x;
  const int wid = tid >> 5;
  const int lane = tid & 31;
  const int p = blockIdx.y;

  uint4* Bhi4 = (uint4*)(smem + PP_BHI);   // [ks][np][lane], np=0..7 (16 nf)
  uint4* Blo4 = (uint4*)(smem + PP_BLO);

  // ---- coalesced fragment copy from global (prebuilt), ONCE ----
  {
    const uint4* sh = g_Wf_hi[p];
    const uint4* sl = g_Wf_lo[p];
    for (int i = tid; i < 2048; i += 128) {
      Bhi4[i] = sh[i];
      Blo4[i] = sl[i];
    }
  }
  __syncthreads();

  const int sub = lane & 7;
  const int rgl = lane >> 3;
  char* tile_hi = smem + PP_AHI + (size_t)wid * 16 * AROW;
  char* tile_lo = smem + PP_ALO + (size_t)wid * 16 * AROW;

  const uint32_t lrow = (lane < 16) ? lane : (lane - 16);
  const uint32_t lcol = (lane < 16) ? 0u : 16u;
  const uint32_t ahi_ld = sbase + PP_AHI + (wid * 16 + lrow) * AROW + lcol;
  const uint32_t alo_ld = sbase + PP_ALO + (wid * 16 + lrow) * AROW + lcol;

  __half* Pp = g_Ph + (size_t)p * NCAP * 128;
  const int ntiles = (nodes + 15) >> 4;
  const int wstride = gridDim.x * 4;

  for (int wt = blockIdx.x * 4 + wid; wt < ntiles; wt += wstride) {
    const int n0 = wt << 4;

    // ---- A split: 16 x-rows -> trunc hi/lo bf16 in AROW layout ----
#pragma unroll
    for (int rg = 0; rg < 4; rg++) {
      const int r = rg * 4 + rgl;
      const int gr = min(n0 + r, nodes - 1);
      const float* xr = x + (size_t)gr * 128;
      char* rhi = tile_hi + (size_t)r * AROW;
      char* rlo = tile_lo + (size_t)r * AROW;
#pragma unroll
      for (int q = 0; q < 4; q++) {
        const int c = q * 32 + sub * 4;
        const float4 v4 = *(const float4*)(xr + c);
        const uint32_t hi01 = __byte_perm(__float_as_uint(v4.x),
                                          __float_as_uint(v4.y), 0x7632);
        const uint32_t hi23 = __byte_perm(__float_as_uint(v4.z),
                                          __float_as_uint(v4.w), 0x7632);
        const float l0 = v4.x - trunc_bf16(v4.x);
        const float l1 = v4.y - trunc_bf16(v4.y);
        const float l2 = v4.z - trunc_bf16(v4.z);
        const float l3 = v4.w - trunc_bf16(v4.w);
        const __nv_bfloat162 lp01 = __floats2bfloat162_rn(l0, l1);
        const __nv_bfloat162 lp23 = __floats2bfloat162_rn(l2, l3);
        const int qb = (q < 2) ? (q * 64 + sub * 8)
                               : (HALF_OFF + (q - 2) * 64 + sub * 8);
        *(uint2*)(rhi + qb) = make_uint2(hi01, hi23);
        *(uint2*)(rlo + qb) =
            make_uint2(*(const uint32_t*)&lp01, *(const uint32_t*)&lp23);
      }
    }
    __syncwarp();

    float acc[16][4];
#pragma unroll
    for (int n = 0; n < 16; n++)
#pragma unroll
      for (int q = 0; q < 4; q++) acc[n][q] = 0.f;

#pragma unroll
    for (int ks = 0; ks < 8; ks++) {
      const uint32_t kb = ks * 32 + ((ks >= 4) ? 16u : 0u);
      uint32_t ah0, ah1, ah2, ah3, al0, al1, al2, al3;
      LDSM4(ah0, ah1, ah2, ah3, ahi_ld + kb);
      LDSM4(al0, al1, al2, al3, alo_ld + kb);
#pragma unroll
      for (int np = 0; np < 8; np++) {
        const uint4 vh = Bhi4[(ks * 8 + np) * 32 + lane];
        const uint4 vl = Blo4[(ks * 8 + np) * 32 + lane];
        MMA16816(acc[2 * np], ah0, ah1, ah2, ah3, vh.x, vh.y);
        MMA16816(acc[2 * np], ah0, ah1, ah2, ah3, vl.x, vl.y);
        MMA16816(acc[2 * np], al0, al1, al2, al3, vh.x, vh.y);
        MMA16816(acc[2 * np + 1], ah0, ah1, ah2, ah3, vh.z, vh.w);
        MMA16816(acc[2 * np + 1], ah0, ah1, ah2, ah3, vl.z, vl.w);
        MMA16816(acc[2 * np + 1], al0, al1, al2, al3, vh.z, vh.w);
      }
    }

    // store D -> g_Ph[p] as fp16 pairs
    const int r0 = n0 + (lane >> 2);
    const int r1 = r0 + 8;
#pragma unroll
    for (int nf = 0; nf < 16; nf++) {
      const int c0 = nf * 8 + (lane & 3) * 2;
      if (r0 < nodes)
        *(__half2*)(Pp + (size_t)r0 * 128 + c0) =
            __floats2half2_rn(acc[nf][0], acc[nf][1]);
      if (r1 < nodes)
        *(__half2*)(Pp + (size_t)r1 * 128 + c0) =
            __floats2half2_rn(acc[nf][2], acc[nf][3]);
    }
    __syncwarp();   // protect this warp's A region before next iteration
  }
}

// ---------------------------------------------------------------------------
// Kernel B: per-group context term (+ b1 folded in), fp16 in/out
// ---------------------------------------------------------------------------
__global__ __launch_bounds__(128) void group_ctx(
    const int* __restrict__ indices, const float* __restrict__ b1, int G) {
  const int g = blockIdx.x;
  if (g >= G) return;
  const int t = threadIdx.x;
  const int* ip = indices + (size_t)g * 25 * 23 + 3;
  const __half* Pc = g_Ph + (size_t)2 * NCAP * 128;

  float s = 0.f;
  int cnt = 0;
#pragma unroll
  for (int kk = 0; kk < 20; kk++) {
    const int id = ip[kk];
    s += __half2float(Pc[(size_t)id * 128 + t]);
    cnt += (id > 0) ? 1 : 0;
  }
  const float norm = (float)(cnt > 0 ? cnt : 1);
  g_Gch[(size_t)g * 128 + t] = __float2half(s / norm + b1[t]);
}

// ---------------------------------------------------------------------------
// Kernel C: warp-independent single-pass fp16 HMMA MLP, 32-row warp tiles.
// Two 16-row subtiles share every B-fragment read (B wf/row halved) while
// 256-thr blocks keep 16 warps/SM (smem 86.8 KB -> 2 blocks/SM).
// ---------------------------------------------------------------------------
#define M_A_OFF 0                          // 8 warps * 32 rows * AROW = 69632
#define M_BF_OFF (8 * 32 * AROW)           // 69632
#define M_BFRAG_U4 1024
#define M_MISC_OFF (M_BF_OFF + M_BFRAG_U4 * 16)   // 86016
#define M_SMEM (M_MISC_OFF + 768)          // 86784

__global__ void __launch_bounds__(256, 2) mlp_main_mma(
    const int* __restrict__ indices,
    const float* __restrict__ b2, const float* __restrict__ W3,
    const float* __restrict__ b3,
    float* __restrict__ out, int N) {
  extern __shared__ char smem[];
  const uint32_t sbase = smem_u32(smem);

  const int tid = threadIdx.x;
  const int wid = tid >> 5;
  const int lane = tid & 31;

  uint4* Bf4 = (uint4*)(smem + M_BF_OFF);    // [ks][np][lane], fp16
  float* b2s = (float*)(smem + M_MISC_OFF);
  float* w3s = b2s + 64;

  // ---- coalesced W2 fp16 fragment copy (prebuilt, table 3) ----
  {
    const uint4* sh = g_Wf_hi[3];
    for (int i = tid; i < M_BFRAG_U4; i += 256) Bf4[i] = sh[i];
  }
  if (tid < 64) { b2s[tid] = b2[tid]; w3s[tid] = W3[tid]; }
  const float b3v = b3[0];
  __syncthreads();

  const char* PaB = (const char*)g_Ph;
  const char* PbB = (const char*)(g_Ph + (size_t)NCAP * 128);
  const char* GcB = (const char*)g_Gch;

  const int sub = lane & 7;          // 16B sub-block (8 fp16 ch) within a row
  const int rgl = lane >> 3;         // row within group of 4
  char* tile_a = smem + M_A_OFF + (size_t)(wid * 32) * AROW;

  const uint32_t lrow = (lane < 16) ? lane : (lane - 16);
  const uint32_t lcol = (lane < 16) ? 0u : 16u;
  const uint32_t a_ld = sbase + M_A_OFF + (wid * 32 + lrow) * AROW + lcol;

  const int NT32 = (N + 31) >> 5;    // 32-row warp tiles
  const int wstride = gridDim.x * 8;

  for (int wt = blockIdx.x * 8 + wid; wt < NT32; wt += wstride) {
    const int rbase = wt << 5;

    // ---- Phase A: fp16 gather 32 rows + relu -> fp16 A tile ----
#pragma unroll
    for (int rg = 0; rg < 8; rg++) {
      const int r = rg * 4 + rgl;
      const int gr = min(rbase + r, N - 1);
      const int i0 = indices[(size_t)gr * 23 + 0];
      const int i1 = indices[(size_t)gr * 23 + 1];
      const int g = gr / 25;
      const char* pa = PaB + (size_t)i0 * 256;
      const char* pb = PbB + (size_t)i1 * 256;
      const char* gc = GcB + (size_t)g * 256;
      char* ra = tile_a + (size_t)r * AROW;
#pragma unroll
      for (int q = 0; q < 2; q++) {
        const int off = q * 128 + sub * 16;   // 8 fp16 channels
        const uint4 ua = *(const uint4*)(pa + off);
        const uint4 ub = *(const uint4*)(pb + off);
        const uint4 ug = *(const uint4*)(gc + off);
        const __half2* ha = (const __half2*)&ua;
        const __half2* hb = (const __half2*)&ub;
        const __half2* hg = (const __half2*)&ug;
        uint32_t hp[4];
#pragma unroll
        for (int j = 0; j < 4; j++) {
          const float2 fa = __half22float2(ha[j]);
          const float2 fb = __half22float2(hb[j]);
          const float2 fg = __half22float2(hg[j]);
          hp[j] = hpack(fmaxf(fa.x + fb.x + fg.x, 0.f),
                        fmaxf(fa.y + fb.y + fg.y, 0.f));
        }
        const int qb = (q == 0) ? (sub * 16) : (HALF_OFF + sub * 16);
        *(uint4*)(ra + qb) = make_uint4(hp[0], hp[1], hp[2], hp[3]);
      }
    }
    __syncwarp();

    // ---- Phase B: single-pass fp16 HMMA, 2 subtiles share each B read ----
    float acc[2][8][4];
#pragma unroll
    for (int t = 0; t < 2; t++)
#pragma unroll
      for (int n = 0; n < 8; n++)
#pragma unroll
        for (int q = 0; q < 4; q++) acc[t][n][q] = 0.f;

#pragma unroll
    for (int ks = 0; ks < 8; ks++) {
      const uint32_t kb = ks * 32 + ((ks >= 4) ? 16u : 0u);
      uint32_t a00, a01, a02, a03, a10, a11, a12, a13;
      LDSM4(a00, a01, a02, a03, a_ld + kb);
      LDSM4(a10, a11, a12, a13, a_ld + 16 * AROW + kb);
#pragma unroll
      for (int np = 0; np < 4; np++) {
        const uint4 vb = Bf4[(ks * 4 + np) * 32 + lane];
        MMA16816H(acc[0][2 * np], a00, a01, a02, a03, vb.x, vb.y);
        MMA16816H(acc[0][2 * np + 1], a00, a01, a02, a03, vb.z, vb.w);
        MMA16816H(acc[1][2 * np], a10, a11, a12, a13, vb.x, vb.y);
        MMA16816H(acc[1][2 * np + 1], a10, a11, a12, a13, vb.z, vb.w);
      }
    }

    // ---- Epilogue (per subtile) ----
#pragma unroll
    for (int t = 0; t < 2; t++) {
      float s0 = 0.f, s1 = 0.f;
#pragma unroll
      for (int n = 0; n < 8; n++) {
        const int c0 = n * 8 + (lane & 3) * 2;
        const float2 b2p = *(const float2*)(b2s + c0);
        const float2 w3p = *(const float2*)(w3s + c0);
        s0 = fmaf(fmaxf(acc[t][n][0] + b2p.x, 0.f), w3p.x, s0);
        s0 = fmaf(fmaxf(acc[t][n][1] + b2p.y, 0.f), w3p.y, s0);
        s1 = fmaf(fmaxf(acc[t][n][2] + b2p.x, 0.f), w3p.x, s1);
        s1 = fmaf(fmaxf(acc[t][n][3] + b2p.y, 0.f), w3p.y, s1);
      }
      s0 += __shfl_xor_sync(0xffffffffu, s0, 1);
      s0 += __shfl_xor_sync(0xffffffffu, s0, 2);
      s1 += __shfl_xor_sync(0xffffffffu, s1, 1);
      s1 += __shfl_xor_sync(0xffffffffu, s1, 2);
      if ((lane & 3) == 0) {
        const int r0 = rbase + t * 16 + (lane >> 2);
        if (r0 < N) out[r0] = s0 + b3v;
        const int r1 = r0 + 8;
        if (r1 < N) out[r1] = s1 + b3v;
      }
    }
    __syncwarp();   // protect smem tile reuse next iteration
  }
}

// ---------------------------------------------------------------------------
extern "C" void kernel_launch(void* const* d_in, const int* in_sizes, int n_in,
                              void* d_out, int out_size) {
  const int* indices = (const int*)d_in[0];
  // d_in[1] = nr (fixed 24)
  const float* x  = (const float*)d_in[2];
  const float* W1 = (const float*)d_in[3];
  const float* b1 = (const float*)d_in[4];
  const float* W2 = (const float*)d_in[5];
  const float* b2 = (const float*)d_in[6];
  const float* W3 = (const float*)d_in[7];
  const float* b3 = (const float*)d_in[8];
  float* out = (float*)d_out;

  const int N = in_sizes[0] / 23;          // 500000
  const int nodes = in_sizes[2] / 128;     // 10000
  const int G = (N - 2) / 25 + 1;          // 20000 groups

  cudaFuncSetAttribute(precompute_P_tc,
                       cudaFuncAttributeMaxDynamicSharedMemorySize, PP_SMEM);
  cudaFuncSetAttribute(mlp_main_mma,
                       cudaFuncAttributeMaxDynamicSharedMemorySize, M_SMEM);

  dim3 gridW(8, 4);
  build_wfrags<<<gridW, 256>>>(W1, W2);
  dim3 gridP(98, 3);                       // persistent: ~2 blocks/SM total
  precompute_P_tc<<<gridP, 128, PP_SMEM>>>(x, nodes);
  group_ctx<<<G, 128>>>(indices, b1, G);
  mlp_main_mma<<<296, 256, M_SMEM>>>(indices, b2, W3, b3, out, N);
}